// round 4
// baseline (speedup 1.0000x reference)
#include <cuda_runtime.h>
#include <cuda_bf16.h>
#include <math.h>
#include <stdint.h>

#define Bsz 2
#define Nn 2048
#define Cc 256
#define COOR 3
#define Hh 8
#define Dd 64
#define Ee 192   // Dd * COOR
#define DI 512   // Hh * Dd
#define BH 16    // Bsz * Hh

#define LDH 72   // smem tile leading dim in halves (144B rows -> conflict-free ldmatrix)

// ---------------- scratch (device globals; no runtime allocation) ----------
__device__ __nv_bfloat16 g_qh[BH * Nn * Ee];
__device__ __nv_bfloat16 g_ql[BH * Nn * Ee];
__device__ __nv_bfloat16 g_kh[BH * Nn * Ee];
__device__ __nv_bfloat16 g_kl[BH * Nn * Ee];
__device__ __nv_bfloat16 g_vh[BH * Ee * Nn];   // transposed: [bh][e][n]
__device__ __nv_bfloat16 g_vl[BH * Ee * Nn];
__device__ float         g_sim[BH * Nn * Nn];  // 256 MiB
__device__ __nv_bfloat16 g_ah[BH * Nn * Nn];   // attn hi
__device__ __nv_bfloat16 g_al[BH * Nn * Nn];   // attn lo
__device__ float         g_ao[BH * Nn * Ee];

// ---------------- helpers ---------------------------------------------------
__device__ __forceinline__ uint32_t s2u(const void* p) {
    uint32_t a;
    asm("{ .reg .u64 t; cvta.to.shared.u64 t, %1; cvt.u32.u64 %0, t; }"
        : "=r"(a) : "l"(p));
    return a;
}
__device__ __forceinline__ void ldm4(uint32_t& r0, uint32_t& r1, uint32_t& r2,
                                     uint32_t& r3, uint32_t addr) {
    asm volatile("ldmatrix.sync.aligned.m8n8.x4.shared.b16 {%0,%1,%2,%3}, [%4];"
                 : "=r"(r0), "=r"(r1), "=r"(r2), "=r"(r3) : "r"(addr));
}
__device__ __forceinline__ void mma16816(float* c, const uint32_t* a, const uint32_t* b) {
    asm volatile(
        "mma.sync.aligned.m16n8k16.row.col.f32.bf16.bf16.f32 "
        "{%0,%1,%2,%3},{%4,%5,%6,%7},{%8,%9},{%0,%1,%2,%3};"
        : "+f"(c[0]), "+f"(c[1]), "+f"(c[2]), "+f"(c[3])
        : "r"(a[0]), "r"(a[1]), "r"(a[2]), "r"(a[3]), "r"(b[0]), "r"(b[1]));
}
__device__ __forceinline__ void cpa16(uint32_t dst, const void* src) {
    asm volatile("cp.async.cg.shared.global [%0], [%1], 16;"
                 :: "r"(dst), "l"(src));
}
__device__ __forceinline__ void cpa_wait() {
    asm volatile("cp.async.commit_group;");
    asm volatile("cp.async.wait_group 0;");
}
__device__ __forceinline__ void split_bf16(float x, __nv_bfloat16& h, __nv_bfloat16& l) {
    h = __float2bfloat16(x);
    l = __float2bfloat16(x - __bfloat162float(h));
}

// ---------------------------------------------------------------------------
// Projections (fp32 SIMT math, bf16 hi/lo emission).
// MODE 0: q/k proj -> hi/lo [bh][n][e]
// MODE 1: v proj   -> hi/lo [bh][e][n]   (transposed for AV B-operand)
// MODE 2: out proj -> fp32 final output
// ---------------------------------------------------------------------------
template<int MODE>
__global__ __launch_bounds__(256)
void vn_proj(const float* __restrict__ in, const float* __restrict__ W,
             float* __restrict__ outF,
             __nv_bfloat16* __restrict__ outH, __nv_bfloat16* __restrict__ outL)
{
    constexpr int K  = (MODE == 2) ? DI : Cc;
    constexpr int NT = K / 64;

    __shared__ float Wt[64][68];
    __shared__ float Xt[16][Ee];

    const int tid   = threadIdx.x;
    const int o0    = blockIdx.x * 64;
    const int ntile = blockIdx.y % (Nn / 16);
    const int b     = blockIdx.y / (Nn / 16);
    const int n0    = ntile * 16;
    const int n_loc = tid >> 4;
    const int o_grp = tid & 15;

    float acc[4][3] = {};

    for (int t = 0; t < NT; ++t) {
        const int k0 = t * 64;
        #pragma unroll
        for (int j = 0; j < 12; ++j) {
            int l   = tid + j * 256;
            int nl  = l / Ee;
            int idx = l - nl * Ee;
            long base;
            if (MODE != 2)
                base = (((long)b * Nn + (n0 + nl)) * Cc + k0) * COOR;
            else
                base = (((long)b * Hh + t) * Nn + (n0 + nl)) * (long)Ee;
            Xt[nl][idx] = in[base + idx];
        }
        #pragma unroll
        for (int j = 0; j < 16; ++j) {
            int l  = tid + j * 256;
            int kk = l & 63;
            int o  = l >> 6;
            Wt[kk][o] = W[(long)(o0 + o) * K + k0 + kk];
        }
        __syncthreads();
        #pragma unroll
        for (int kk = 0; kk < 64; ++kk) {
            float x0 = Xt[n_loc][kk*3 + 0];
            float x1 = Xt[n_loc][kk*3 + 1];
            float x2 = Xt[n_loc][kk*3 + 2];
            float4 w = *(const float4*)&Wt[kk][o_grp * 4];
            acc[0][0] += w.x * x0; acc[0][1] += w.x * x1; acc[0][2] += w.x * x2;
            acc[1][0] += w.y * x0; acc[1][1] += w.y * x1; acc[1][2] += w.y * x2;
            acc[2][0] += w.z * x0; acc[2][1] += w.z * x1; acc[2][2] += w.z * x2;
            acc[3][0] += w.w * x0; acc[3][1] += w.w * x1; acc[3][2] += w.w * x2;
        }
        __syncthreads();
    }

    const int n = n0 + n_loc;
    #pragma unroll
    for (int u = 0; u < 4; ++u) {
        int o = o0 + o_grp * 4 + u;
        if (MODE == 2) {
            float* dst = &outF[(((long)b * Nn + n) * Cc + o) * (long)COOR];
            dst[0] = acc[u][0]; dst[1] = acc[u][1]; dst[2] = acc[u][2];
        } else {
            int h = o >> 6, d = o & 63;
            long bh = b * Hh + h;
            #pragma unroll
            for (int c = 0; c < 3; ++c) {
                __nv_bfloat16 hi, lo;
                split_bf16(acc[u][c], hi, lo);
                long idx;
                if (MODE == 0) idx = (bh * Nn + n) * Ee + d * 3 + c;
                else           idx = (bh * Ee + d * 3 + c) * Nn + n;
                outH[idx] = hi; outL[idx] = lo;
            }
        }
    }
}

// ---------------------------------------------------------------------------
// QK^T via HMMA (split bf16): sim = scale * q k^T.
// CTA tile 128x128, K=192 in 3 chunks of 64.  8 warps (2x4), warp tile 64x32.
// bf16 operands precomputed; staging = pure cp.async copy.
// ---------------------------------------------------------------------------
__global__ __launch_bounds__(256)
void vn_qk(const __nv_bfloat16* __restrict__ qh, const __nv_bfloat16* __restrict__ ql,
           const __nv_bfloat16* __restrict__ kh, const __nv_bfloat16* __restrict__ kl,
           float* __restrict__ sim, float scale)
{
    extern __shared__ __align__(16) char sm[];
    const int TB = 128 * LDH * 2;          // 18432 bytes per tile
    uint32_t sAh = s2u(sm);
    uint32_t sAl = sAh + TB;
    uint32_t sBh = sAh + 2 * TB;
    uint32_t sBl = sAh + 3 * TB;

    const int tid = threadIdx.x, lane = tid & 31, wid = tid >> 5;
    const int wm = wid >> 2, wn = wid & 3;        // 2 x 4 warp grid
    const int j0 = blockIdx.x * 128, i0 = blockIdx.y * 128, bh = blockIdx.z;

    const __nv_bfloat16* Ah = qh + ((long)bh * Nn + i0) * Ee;
    const __nv_bfloat16* Al = ql + ((long)bh * Nn + i0) * Ee;
    const __nv_bfloat16* Bh = kh + ((long)bh * Nn + j0) * Ee;
    const __nv_bfloat16* Bl = kl + ((long)bh * Nn + j0) * Ee;

    float acc[4][4][4] = {};

    const int lrow = lane & 15;
    const int lcol8 = (lane >> 4) << 3;

    for (int ch = 0; ch < 3; ++ch) {
        const int kc = ch * 64;
        // 4 tiles x 1024 16B-segments, 4 per thread per tile
        #pragma unroll
        for (int s = 0; s < 4; ++s) {
            int seg = tid + s * 256;
            int row = seg >> 3, sg = (seg & 7) << 3;   // sg in halves
            uint32_t doff = (uint32_t)(row * LDH + sg) * 2;
            long goff = (long)row * Ee + kc + sg;
            cpa16(sAh + doff, Ah + goff);
            cpa16(sAl + doff, Al + goff);
            cpa16(sBh + doff, Bh + goff);
            cpa16(sBl + doff, Bl + goff);
        }
        cpa_wait();
        __syncthreads();

        #pragma unroll
        for (int ks = 0; ks < 4; ++ks) {
            const int kcol = ks * 16 + lcol8;
            uint32_t ah[4][4], al[4][4];
            #pragma unroll
            for (int mt = 0; mt < 4; ++mt) {
                uint32_t r = (wm * 64 + mt * 16 + lrow) * LDH + kcol;
                ldm4(ah[mt][0], ah[mt][1], ah[mt][2], ah[mt][3], sAh + r * 2);
                ldm4(al[mt][0], al[mt][1], al[mt][2], al[mt][3], sAl + r * 2);
            }
            uint32_t bhf[4][2], blf[4][2];
            #pragma unroll
            for (int g = 0; g < 2; ++g) {
                uint32_t r = (wn * 32 + g * 16 + lrow) * LDH + kcol;
                uint32_t r0, r1, r2, r3;
                ldm4(r0, r1, r2, r3, sBh + r * 2);
                bhf[g*2][0] = r0; bhf[g*2][1] = r2;
                bhf[g*2+1][0] = r1; bhf[g*2+1][1] = r3;
                ldm4(r0, r1, r2, r3, sBl + r * 2);
                blf[g*2][0] = r0; blf[g*2][1] = r2;
                blf[g*2+1][0] = r1; blf[g*2+1][1] = r3;
            }
            #pragma unroll
            for (int mt = 0; mt < 4; ++mt)
                #pragma unroll
                for (int nt = 0; nt < 4; ++nt) {
                    mma16816(acc[mt][nt], ah[mt], bhf[nt]);
                    mma16816(acc[mt][nt], ah[mt], blf[nt]);
                    mma16816(acc[mt][nt], al[mt], bhf[nt]);
                }
        }
        __syncthreads();
    }

    #pragma unroll
    for (int mt = 0; mt < 4; ++mt) {
        #pragma unroll
        for (int nt = 0; nt < 4; ++nt) {
            int row = i0 + wm * 64 + mt * 16 + (lane >> 2);
            int col = j0 + wn * 32 + nt * 8 + (lane & 3) * 2;
            float* base = sim + ((long)bh * Nn + row) * Nn + col;
            *(float2*)base = make_float2(acc[mt][nt][0] * scale, acc[mt][nt][1] * scale);
            *(float2*)(base + 8L * Nn) =
                make_float2(acc[mt][nt][2] * scale, acc[mt][nt][3] * scale);
        }
    }
}

// ---------------------------------------------------------------------------
// AV via HMMA (split bf16): ao[i][e] = sum_j attn[i][j] vt[e][j].
// CTA tile 64x192, K=2048 in 32 chunks of 64.  8 warps (2x4), warp tile 32x48.
// ---------------------------------------------------------------------------
__global__ __launch_bounds__(256)
void vn_av(const __nv_bfloat16* __restrict__ ah_g, const __nv_bfloat16* __restrict__ al_g,
           const __nv_bfloat16* __restrict__ vh_g, const __nv_bfloat16* __restrict__ vl_g,
           float* __restrict__ ao)
{
    extern __shared__ __align__(16) char sm[];
    const int TA = 64 * LDH * 2;           //  9216 bytes
    const int TBB = 192 * LDH * 2;         // 27648 bytes
    uint32_t sAh = s2u(sm);
    uint32_t sAl = sAh + TA;
    uint32_t sBh = sAh + 2 * TA;
    uint32_t sBl = sAh + 2 * TA + TBB;

    const int tid = threadIdx.x, lane = tid & 31, wid = tid >> 5;
    const int wm = wid >> 2, wn = wid & 3;
    const int i0 = blockIdx.x * 64, bh = blockIdx.y;

    const __nv_bfloat16* Ah = ah_g + ((long)bh * Nn + i0) * Nn;
    const __nv_bfloat16* Al = al_g + ((long)bh * Nn + i0) * Nn;
    const __nv_bfloat16* Bh = vh_g + (long)bh * Ee * Nn;
    const __nv_bfloat16* Bl = vl_g + (long)bh * Ee * Nn;

    float acc[2][6][4] = {};

    const int lrow = lane & 15;
    const int lcol8 = (lane >> 4) << 3;

    for (int ch = 0; ch < 32; ++ch) {
        const int jc = ch * 64;
        // A tiles: 512 segs each (2/thread); B tiles: 1536 segs each (6/thread)
        #pragma unroll
        for (int s = 0; s < 2; ++s) {
            int seg = tid + s * 256;
            int row = seg >> 3, sg = (seg & 7) << 3;
            uint32_t doff = (uint32_t)(row * LDH + sg) * 2;
            long goff = (long)row * Nn + jc + sg;
            cpa16(sAh + doff, Ah + goff);
            cpa16(sAl + doff, Al + goff);
        }
        #pragma unroll
        for (int s = 0; s < 6; ++s) {
            int seg = tid + s * 256;
            int row = seg >> 3, sg = (seg & 7) << 3;
            uint32_t doff = (uint32_t)(row * LDH + sg) * 2;
            long goff = (long)row * Nn + jc + sg;
            cpa16(sBh + doff, Bh + goff);
            cpa16(sBl + doff, Bl + goff);
        }
        cpa_wait();
        __syncthreads();

        #pragma unroll
        for (int ks = 0; ks < 4; ++ks) {
            const int kcol = ks * 16 + lcol8;
            uint32_t a_h[2][4], a_l[2][4];
            #pragma unroll
            for (int mt = 0; mt < 2; ++mt) {
                uint32_t r = (wm * 32 + mt * 16 + lrow) * LDH + kcol;
                ldm4(a_h[mt][0], a_h[mt][1], a_h[mt][2], a_h[mt][3], sAh + r * 2);
                ldm4(a_l[mt][0], a_l[mt][1], a_l[mt][2], a_l[mt][3], sAl + r * 2);
            }
            uint32_t bhf[6][2], blf[6][2];
            #pragma unroll
            for (int g = 0; g < 3; ++g) {
                uint32_t r = (wn * 48 + g * 16 + lrow) * LDH + kcol;
                uint32_t r0, r1, r2, r3;
                ldm4(r0, r1, r2, r3, sBh + r * 2);
                bhf[g*2][0] = r0; bhf[g*2][1] = r2;
                bhf[g*2+1][0] = r1; bhf[g*2+1][1] = r3;
                ldm4(r0, r1, r2, r3, sBl + r * 2);
                blf[g*2][0] = r0; blf[g*2][1] = r2;
                blf[g*2+1][0] = r1; blf[g*2+1][1] = r3;
            }
            #pragma unroll
            for (int mt = 0; mt < 2; ++mt)
                #pragma unroll
                for (int nt = 0; nt < 6; ++nt) {
                    mma16816(acc[mt][nt], a_h[mt], bhf[nt]);
                    mma16816(acc[mt][nt], a_h[mt], blf[nt]);
                    mma16816(acc[mt][nt], a_l[mt], bhf[nt]);
                }
        }
        __syncthreads();
    }

    #pragma unroll
    for (int mt = 0; mt < 2; ++mt) {
        #pragma unroll
        for (int nt = 0; nt < 6; ++nt) {
            int row = i0 + wm * 32 + mt * 16 + (lane >> 2);
            int col = wn * 48 + nt * 8 + (lane & 3) * 2;
            float* base = ao + ((long)bh * Nn + row) * Ee + col;
            *(float2*)base = make_float2(acc[mt][nt][0], acc[mt][nt][1]);
            *(float2*)(base + 8L * Ee) = make_float2(acc[mt][nt][2], acc[mt][nt][3]);
        }
    }
}

// ---------------------------------------------------------------------------
// Row softmax over 2048-wide rows of g_sim; emits attn as bf16 hi/lo.
// ---------------------------------------------------------------------------
__global__ __launch_bounds__(256)
void softmax_rows(const float* __restrict__ sim,
                  __nv_bfloat16* __restrict__ ah, __nv_bfloat16* __restrict__ al)
{
    __shared__ float redm[8];
    __shared__ float reds[8];

    const long row = blockIdx.x;
    const float* p = sim + row * (long)Nn;
    const int tid  = threadIdx.x;
    const int lane = tid & 31;
    const int wid  = tid >> 5;

    float v[8];
    float m = -1e30f;
    #pragma unroll
    for (int r = 0; r < 8; ++r) {
        v[r] = p[tid + r * 256];
        m = fmaxf(m, v[r]);
    }
    #pragma unroll
    for (int off = 16; off > 0; off >>= 1)
        m = fmaxf(m, __shfl_xor_sync(0xffffffffu, m, off));
    if (lane == 0) redm[wid] = m;
    __syncthreads();
    float bm = redm[0];
    #pragma unroll
    for (int i = 1; i < 8; ++i) bm = fmaxf(bm, redm[i]);

    float s = 0.f;
    #pragma unroll
    for (int r = 0; r < 8; ++r) {
        v[r] = __expf(v[r] - bm);
        s += v[r];
    }
    #pragma unroll
    for (int off = 16; off > 0; off >>= 1)
        s += __shfl_xor_sync(0xffffffffu, s, off);
    if (lane == 0) reds[wid] = s;
    __syncthreads();
    float total = 0.f;
    #pragma unroll
    for (int i = 0; i < 8; ++i) total += reds[i];
    const float inv = 1.0f / total;

    #pragma unroll
    for (int r = 0; r < 8; ++r) {
        float val = v[r] * inv;
        __nv_bfloat16 hi, lo;
        split_bf16(val, hi, lo);
        long idx = row * (long)Nn + tid + r * 256;
        ah[idx] = hi;
        al[idx] = lo;
    }
}

// ---------------------------------------------------------------------------
extern "C" void kernel_launch(void* const* d_in, const int* in_sizes, int n_in,
                              void* d_out, int out_size)
{
    const float* x  = (const float*)d_in[0];
    const float* Wq = (const float*)d_in[1];
    const float* Wk = (const float*)d_in[2];
    const float* Wv = (const float*)d_in[3];
    const float* Wo = (const float*)d_in[4];
    float* y = (float*)d_out;

    __nv_bfloat16 *qh, *ql, *kh, *kl, *vh, *vl, *ath, *atl;
    float *sim, *ao;
    cudaGetSymbolAddress((void**)&qh,  g_qh);
    cudaGetSymbolAddress((void**)&ql,  g_ql);
    cudaGetSymbolAddress((void**)&kh,  g_kh);
    cudaGetSymbolAddress((void**)&kl,  g_kl);
    cudaGetSymbolAddress((void**)&vh,  g_vh);
    cudaGetSymbolAddress((void**)&vl,  g_vl);
    cudaGetSymbolAddress((void**)&ath, g_ah);
    cudaGetSymbolAddress((void**)&atl, g_al);
    cudaGetSymbolAddress((void**)&sim, g_sim);
    cudaGetSymbolAddress((void**)&ao,  g_ao);

    const int QK_SMEM = 4 * (128 * LDH * 2);                       // 73728
    const int AV_SMEM = 2 * (64 * LDH * 2) + 2 * (192 * LDH * 2);  // 73728
    cudaFuncSetAttribute(vn_qk, cudaFuncAttributeMaxDynamicSharedMemorySize, QK_SMEM);
    cudaFuncSetAttribute(vn_av, cudaFuncAttributeMaxDynamicSharedMemorySize, AV_SMEM);

    dim3 blk(256);

    // projections (emit bf16 hi/lo; V transposed)
    dim3 gp(DI / 64, Bsz * (Nn / 16));
    vn_proj<0><<<gp, blk>>>(x, Wq, nullptr, qh, ql);
    vn_proj<0><<<gp, blk>>>(x, Wk, nullptr, kh, kl);
    vn_proj<1><<<gp, blk>>>(x, Wv, nullptr, vh, vl);

    // sim = scale * q k^T
    const float scale = 1.0f / sqrtf((float)Ee);
    dim3 g2(Nn / 128, Nn / 128, BH);
    vn_qk<<<g2, blk, QK_SMEM>>>(qh, ql, kh, kl, sim, scale);

    // softmax -> bf16 hi/lo attn
    softmax_rows<<<BH * Nn, blk>>>(sim, ath, atl);

    // ao = attn @ v
    dim3 g3(Nn / 64, BH);
    vn_av<<<g3, blk, AV_SMEM>>>(ath, atl, vh, vl, ao);

    // final projection
    dim3 g4(Cc / 64, Bsz * (Nn / 16));
    vn_proj<2><<<g4, blk>>>(ao, Wo, y, nullptr, nullptr);
}

// round 8
// speedup vs baseline: 1.0598x; 1.0598x over previous
#include <cuda_runtime.h>
#include <cuda_bf16.h>
#include <math.h>
#include <stdint.h>

#define Bsz 2
#define Nn 2048
#define Cc 256
#define COOR 3
#define Hh 8
#define Dd 64
#define Ee 192   // Dd * COOR
#define DI 512   // Hh * Dd
#define BH 16    // Bsz * Hh

// smem strides (in halves) and byte offsets for the fused kernel
#define LDQ 200  // Q/K tiles: 192 cols + 8 pad  -> 400B rows, conflict-free ldmatrix
#define LDV 72   // V tile: 64 cols + 8 pad      -> 144B rows, conflict-free ldmatrix
#define OQH 0
#define OQL 51200
#define OKH 102400
#define OKL 128000
#define OVH 153600
#define OVL 181248
#define SMEM_TOT 208896

// ---------------- scratch (device globals; no runtime allocation) ----------
__device__ __nv_bfloat16 g_qh[BH * Nn * Ee];
__device__ __nv_bfloat16 g_ql[BH * Nn * Ee];
__device__ __nv_bfloat16 g_kh[BH * Nn * Ee];
__device__ __nv_bfloat16 g_kl[BH * Nn * Ee];
__device__ __nv_bfloat16 g_vh[BH * Ee * Nn];   // transposed: [bh][e][n]
__device__ __nv_bfloat16 g_vl[BH * Ee * Nn];
__device__ float         g_ao[BH * Nn * Ee];

// ---------------- helpers ---------------------------------------------------
__device__ __forceinline__ uint32_t s2u(const void* p) {
    uint32_t a;
    asm("{ .reg .u64 t; cvta.to.shared.u64 t, %1; cvt.u32.u64 %0, t; }"
        : "=r"(a) : "l"(p));
    return a;
}
__device__ __forceinline__ void ldm4(uint32_t& r0, uint32_t& r1, uint32_t& r2,
                                     uint32_t& r3, uint32_t addr) {
    asm volatile("ldmatrix.sync.aligned.m8n8.x4.shared.b16 {%0,%1,%2,%3}, [%4];"
                 : "=r"(r0), "=r"(r1), "=r"(r2), "=r"(r3) : "r"(addr));
}
__device__ __forceinline__ void mma16816(float* c, const uint32_t* a, const uint32_t* b) {
    asm volatile(
        "mma.sync.aligned.m16n8k16.row.col.f32.bf16.bf16.f32 "
        "{%0,%1,%2,%3},{%4,%5,%6,%7},{%8,%9},{%0,%1,%2,%3};"
        : "+f"(c[0]), "+f"(c[1]), "+f"(c[2]), "+f"(c[3])
        : "r"(a[0]), "r"(a[1]), "r"(a[2]), "r"(a[3]), "r"(b[0]), "r"(b[1]));
}
__device__ __forceinline__ void cpa16(uint32_t dst, const void* src) {
    asm volatile("cp.async.cg.shared.global [%0], [%1], 16;"
                 :: "r"(dst), "l"(src));
}
__device__ __forceinline__ void cpa_wait() {
    asm volatile("cp.async.commit_group;");
    asm volatile("cp.async.wait_group 0;");
}
__device__ __forceinline__ void split_bf16(float x, __nv_bfloat16& h, __nv_bfloat16& l) {
    h = __float2bfloat16(x);
    l = __float2bfloat16(x - __bfloat162float(h));
}
// pack (a,b) to bf16x2 hi reg; return residuals for the lo pass
__device__ __forceinline__ uint32_t pack_hi(float a, float b, float& ra, float& rb) {
    __nv_bfloat16 ha = __float2bfloat16(a), hb = __float2bfloat16(b);
    ra = a - __bfloat162float(ha);
    rb = b - __bfloat162float(hb);
    __nv_bfloat162 p(ha, hb);
    return *(uint32_t*)&p;
}
__device__ __forceinline__ uint32_t pack_lo(float ra, float rb) {
    __nv_bfloat162 p(__float2bfloat16(ra), __float2bfloat16(rb));
    return *(uint32_t*)&p;
}

// ---------------------------------------------------------------------------
// Projections (fp32 SIMT math, bf16 hi/lo emission).
// MODE 0: q/k proj -> hi/lo [bh][n][e]
// MODE 1: v proj   -> hi/lo [bh][e][n]   (transposed)
// MODE 2: out proj -> fp32 final output
// ---------------------------------------------------------------------------
template<int MODE>
__global__ __launch_bounds__(256)
void vn_proj(const float* __restrict__ in, const float* __restrict__ W,
             float* __restrict__ outF,
             __nv_bfloat16* __restrict__ outH, __nv_bfloat16* __restrict__ outL)
{
    constexpr int K  = (MODE == 2) ? DI : Cc;
    constexpr int NT = K / 64;

    __shared__ float Wt[64][68];
    __shared__ float Xt[16][Ee];

    const int tid   = threadIdx.x;
    const int o0    = blockIdx.x * 64;
    const int ntile = blockIdx.y % (Nn / 16);
    const int b     = blockIdx.y / (Nn / 16);
    const int n0    = ntile * 16;
    const int n_loc = tid >> 4;
    const int o_grp = tid & 15;

    float acc[4][3] = {};

    for (int t = 0; t < NT; ++t) {
        const int k0 = t * 64;
        #pragma unroll
        for (int j = 0; j < 12; ++j) {
            int l   = tid + j * 256;
            int nl  = l / Ee;
            int idx = l - nl * Ee;
            long base;
            if (MODE != 2)
                base = (((long)b * Nn + (n0 + nl)) * Cc + k0) * COOR;
            else
                base = (((long)b * Hh + t) * Nn + (n0 + nl)) * (long)Ee;
            Xt[nl][idx] = in[base + idx];
        }
        #pragma unroll
        for (int j = 0; j < 16; ++j) {
            int l  = tid + j * 256;
            int kk = l & 63;
            int o  = l >> 6;
            Wt[kk][o] = W[(long)(o0 + o) * K + k0 + kk];
        }
        __syncthreads();
        #pragma unroll
        for (int kk = 0; kk < 64; ++kk) {
            float x0 = Xt[n_loc][kk*3 + 0];
            float x1 = Xt[n_loc][kk*3 + 1];
            float x2 = Xt[n_loc][kk*3 + 2];
            float4 w = *(const float4*)&Wt[kk][o_grp * 4];
            acc[0][0] += w.x * x0; acc[0][1] += w.x * x1; acc[0][2] += w.x * x2;
            acc[1][0] += w.y * x0; acc[1][1] += w.y * x1; acc[1][2] += w.y * x2;
            acc[2][0] += w.z * x0; acc[2][1] += w.z * x1; acc[2][2] += w.z * x2;
            acc[3][0] += w.w * x0; acc[3][1] += w.w * x1; acc[3][2] += w.w * x2;
        }
        __syncthreads();
    }

    const int n = n0 + n_loc;
    #pragma unroll
    for (int u = 0; u < 4; ++u) {
        int o = o0 + o_grp * 4 + u;
        if (MODE == 2) {
            float* dst = &outF[(((long)b * Nn + n) * Cc + o) * (long)COOR];
            dst[0] = acc[u][0]; dst[1] = acc[u][1]; dst[2] = acc[u][2];
        } else {
            int h = o >> 6, d = o & 63;
            long bh = b * Hh + h;
            #pragma unroll
            for (int c = 0; c < 3; ++c) {
                __nv_bfloat16 hi, lo;
                split_bf16(acc[u][c], hi, lo);
                long idx;
                if (MODE == 0) idx = (bh * Nn + n) * Ee + d * 3 + c;
                else           idx = (bh * Ee + d * 3 + c) * Nn + n;
                outH[idx] = hi; outL[idx] = lo;
            }
        }
    }
}

// ---------------------------------------------------------------------------
// Fused flash attention: ao = softmax(scale * q k^T) @ v.
// CTA: 128 query rows x full Ee, loop over 32 j-chunks of 64.
// 8 warps; warp tile = 16 rows x all 64 j (softmax warp-local).
// P converts C-frag -> A-frag in registers (no smem round trip).
// ---------------------------------------------------------------------------
__global__ __launch_bounds__(256, 1)
void vn_flash(const __nv_bfloat16* __restrict__ qh, const __nv_bfloat16* __restrict__ ql,
              const __nv_bfloat16* __restrict__ kh, const __nv_bfloat16* __restrict__ kl,
              const __nv_bfloat16* __restrict__ vh, const __nv_bfloat16* __restrict__ vl,
              float* __restrict__ ao, float scale)
{
    extern __shared__ __align__(16) char sm[];
    const uint32_t sb = s2u(sm);
    const int tid = threadIdx.x, lane = tid & 31, w = tid >> 5;
    const int i0 = blockIdx.x * 128, bh = blockIdx.y;
    const int lrow = lane & 15, lc8 = (lane >> 4) << 3;

    // stage Q tile (128 x 192, hi+lo) — persistent
    {
        const __nv_bfloat16* Qh = qh + ((long)bh * Nn + i0) * Ee;
        const __nv_bfloat16* Ql = ql + ((long)bh * Nn + i0) * Ee;
        for (int s = tid; s < 128 * 24; s += 256) {
            int row = s / 24, seg = s - row * 24;
            uint32_t doff = (uint32_t)(row * LDQ + seg * 8) * 2;
            long g = (long)row * Ee + seg * 8;
            cpa16(sb + OQH + doff, Qh + g);
            cpa16(sb + OQL + doff, Ql + g);
        }
    }

    float O[24][4];
    #pragma unroll
    for (int i = 0; i < 24; ++i) { O[i][0]=0.f; O[i][1]=0.f; O[i][2]=0.f; O[i][3]=0.f; }
    float m0 = -1e30f, m1 = -1e30f, l0 = 0.f, l1 = 0.f;

    const __nv_bfloat16* Kh = kh + (long)bh * Nn * Ee;
    const __nv_bfloat16* Kl = kl + (long)bh * Nn * Ee;
    const __nv_bfloat16* Vh = vh + (long)bh * Ee * Nn;
    const __nv_bfloat16* Vl = vl + (long)bh * Ee * Nn;

    for (int ch = 0; ch < 32; ++ch) {
        const int jc = ch * 64;
        // stage K chunk (64 x 192) and V chunk (192 x 64), hi+lo
        #pragma unroll
        for (int it = 0; it < 6; ++it) {
            int s = tid + it * 256;
            {
                int row = s / 24, seg = s - row * 24;      // K: row < 64
                uint32_t doff = (uint32_t)(row * LDQ + seg * 8) * 2;
                long g = (long)(jc + row) * Ee + seg * 8;
                cpa16(sb + OKH + doff, Kh + g);
                cpa16(sb + OKL + doff, Kl + g);
            }
            {
                int row = s >> 3, seg = s & 7;             // V: row < 192
                uint32_t doff = (uint32_t)(row * LDV + seg * 8) * 2;
                long g = (long)row * Nn + jc + seg * 8;
                cpa16(sb + OVH + doff, Vh + g);
                cpa16(sb + OVL + doff, Vl + g);
            }
        }
        cpa_wait();
        __syncthreads();

        // ---- S = q k^T  (16 rows x 64 cols per warp) ----
        float S[8][4];
        #pragma unroll
        for (int i = 0; i < 8; ++i) { S[i][0]=0.f; S[i][1]=0.f; S[i][2]=0.f; S[i][3]=0.f; }
        #pragma unroll
        for (int ks = 0; ks < 12; ++ks) {
            const int kcol = ks * 16 + lc8;
            uint32_t qah[4], qal[4];
            uint32_t r = (uint32_t)((w * 16 + lrow) * LDQ + kcol) * 2;
            ldm4(qah[0], qah[1], qah[2], qah[3], sb + OQH + r);
            ldm4(qal[0], qal[1], qal[2], qal[3], sb + OQL + r);
            #pragma unroll
            for (int g = 0; g < 4; ++g) {
                uint32_t rb = (uint32_t)((g * 16 + lrow) * LDQ + kcol) * 2;
                uint32_t b0, b1, b2, b3;
                ldm4(b0, b1, b2, b3, sb + OKH + rb);
                uint32_t bh0[2] = {b0, b2}, bh1[2] = {b1, b3};
                ldm4(b0, b1, b2, b3, sb + OKL + rb);
                uint32_t bl0[2] = {b0, b2}, bl1[2] = {b1, b3};
                mma16816(S[2*g],   qah, bh0);
                mma16816(S[2*g],   qah, bl0);
                mma16816(S[2*g],   qal, bh0);
                mma16816(S[2*g+1], qah, bh1);
                mma16816(S[2*g+1], qah, bl1);
                mma16816(S[2*g+1], qal, bh1);
            }
        }

        // ---- online softmax (warp-local rows) ----
        float pm0 = -1e30f, pm1 = -1e30f;
        #pragma unroll
        for (int nt = 0; nt < 8; ++nt) {
            S[nt][0] *= scale; S[nt][1] *= scale; S[nt][2] *= scale; S[nt][3] *= scale;
            pm0 = fmaxf(pm0, fmaxf(S[nt][0], S[nt][1]));
            pm1 = fmaxf(pm1, fmaxf(S[nt][2], S[nt][3]));
        }
        pm0 = fmaxf(pm0, __shfl_xor_sync(0xffffffffu, pm0, 1));
        pm0 = fmaxf(pm0, __shfl_xor_sync(0xffffffffu, pm0, 2));
        pm1 = fmaxf(pm1, __shfl_xor_sync(0xffffffffu, pm1, 1));
        pm1 = fmaxf(pm1, __shfl_xor_sync(0xffffffffu, pm1, 2));
        const float nm0 = fmaxf(m0, pm0), nm1 = fmaxf(m1, pm1);
        const float a0 = __expf(m0 - nm0), a1 = __expf(m1 - nm1);
        float rs0 = 0.f, rs1 = 0.f;
        #pragma unroll
        for (int nt = 0; nt < 8; ++nt) {
            S[nt][0] = __expf(S[nt][0] - nm0);
            S[nt][1] = __expf(S[nt][1] - nm0);
            S[nt][2] = __expf(S[nt][2] - nm1);
            S[nt][3] = __expf(S[nt][3] - nm1);
            rs0 += S[nt][0] + S[nt][1];
            rs1 += S[nt][2] + S[nt][3];
        }
        rs0 += __shfl_xor_sync(0xffffffffu, rs0, 1);
        rs0 += __shfl_xor_sync(0xffffffffu, rs0, 2);
        rs1 += __shfl_xor_sync(0xffffffffu, rs1, 1);
        rs1 += __shfl_xor_sync(0xffffffffu, rs1, 2);
        l0 = l0 * a0 + rs0;
        l1 = l1 * a1 + rs1;
        m0 = nm0; m1 = nm1;
        #pragma unroll
        for (int nt = 0; nt < 24; ++nt) {
            O[nt][0] *= a0; O[nt][1] *= a0; O[nt][2] *= a1; O[nt][3] *= a1;
        }

        // ---- pack P into bf16 hi/lo A-fragments (C->A identity mapping) ----
        uint32_t pah[4][4], pal[4][4];
        #pragma unroll
        for (int ks = 0; ks < 4; ++ks) {
            const int e2 = 2 * ks, o2 = 2 * ks + 1;
            float ra, rb;
            pah[ks][0] = pack_hi(S[e2][0], S[e2][1], ra, rb); pal[ks][0] = pack_lo(ra, rb);
            pah[ks][1] = pack_hi(S[e2][2], S[e2][3], ra, rb); pal[ks][1] = pack_lo(ra, rb);
            pah[ks][2] = pack_hi(S[o2][0], S[o2][1], ra, rb); pal[ks][2] = pack_lo(ra, rb);
            pah[ks][3] = pack_hi(S[o2][2], S[o2][3], ra, rb); pal[ks][3] = pack_lo(ra, rb);
        }

        // ---- O += P @ V ----
        #pragma unroll
        for (int ks = 0; ks < 4; ++ks) {
            const int kcol = ks * 16 + lc8;
            #pragma unroll
            for (int gg = 0; gg < 12; ++gg) {
                uint32_t rb = (uint32_t)((gg * 16 + lrow) * LDV + kcol) * 2;
                uint32_t b0, b1, b2, b3;
                ldm4(b0, b1, b2, b3, sb + OVH + rb);
                uint32_t vh0[2] = {b0, b2}, vh1[2] = {b1, b3};
                ldm4(b0, b1, b2, b3, sb + OVL + rb);
                uint32_t vl0[2] = {b0, b2}, vl1[2] = {b1, b3};
                mma16816(O[2*gg],   pah[ks], vh0);
                mma16816(O[2*gg],   pah[ks], vl0);
                mma16816(O[2*gg],   pal[ks], vh0);
                mma16816(O[2*gg+1], pah[ks], vh1);
                mma16816(O[2*gg+1], pah[ks], vl1);
                mma16816(O[2*gg+1], pal[ks], vh1);
            }
        }
        __syncthreads();
    }

    // ---- epilogue: O /= l -> ao ----
    const float inv0 = 1.f / l0, inv1 = 1.f / l1;
    const int rowg = i0 + w * 16 + (lane >> 2);
    const long base = ((long)bh * Nn + rowg) * Ee;
    #pragma unroll
    for (int nt = 0; nt < 24; ++nt) {
        int col = nt * 8 + (lane & 3) * 2;
        *(float2*)(ao + base + col) =
            make_float2(O[nt][0] * inv0, O[nt][1] * inv0);
        *(float2*)(ao + base + 8L * Ee + col) =
            make_float2(O[nt][2] * inv1, O[nt][3] * inv1);
    }
}

// ---------------------------------------------------------------------------
extern "C" void kernel_launch(void* const* d_in, const int* in_sizes, int n_in,
                              void* d_out, int out_size)
{
    const float* x  = (const float*)d_in[0];
    const float* Wq = (const float*)d_in[1];
    const float* Wk = (const float*)d_in[2];
    const float* Wv = (const float*)d_in[3];
    const float* Wo = (const float*)d_in[4];
    float* y = (float*)d_out;

    __nv_bfloat16 *qh, *ql, *kh, *kl, *vh, *vl;
    float *ao;
    cudaGetSymbolAddress((void**)&qh, g_qh);
    cudaGetSymbolAddress((void**)&ql, g_ql);
    cudaGetSymbolAddress((void**)&kh, g_kh);
    cudaGetSymbolAddress((void**)&kl, g_kl);
    cudaGetSymbolAddress((void**)&vh, g_vh);
    cudaGetSymbolAddress((void**)&vl, g_vl);
    cudaGetSymbolAddress((void**)&ao, g_ao);

    cudaFuncSetAttribute(vn_flash, cudaFuncAttributeMaxDynamicSharedMemorySize, SMEM_TOT);

    dim3 blk(256);

    // projections (emit bf16 hi/lo; V transposed)
    dim3 gp(DI / 64, Bsz * (Nn / 16));
    vn_proj<0><<<gp, blk>>>(x, Wq, nullptr, qh, ql);
    vn_proj<0><<<gp, blk>>>(x, Wk, nullptr, kh, kl);
    vn_proj<1><<<gp, blk>>>(x, Wv, nullptr, vh, vl);

    // fused attention
    const float scale = 1.0f / sqrtf((float)Ee);
    dim3 gf(Nn / 128, BH);
    vn_flash<<<gf, blk, SMEM_TOT>>>(qh, ql, kh, kl, vh, vl, ao, scale);

    // final projection
    dim3 g4(Cc / 64, Bsz * (Nn / 16));
    vn_proj<2><<<g4, blk>>>(ao, Wo, y, nullptr, nullptr);
}

// round 10
// speedup vs baseline: 1.4555x; 1.3733x over previous
#include <cuda_runtime.h>
#include <cuda_bf16.h>
#include <math.h>
#include <stdint.h>

#define Bsz 2
#define Nn 2048
#define Cc 256
#define COOR 3
#define Hh 8
#define Dd 64
#define Ee 192   // Dd * COOR
#define DI 512   // Hh * Dd
#define BH 16    // Bsz * Hh
#define Jb 6144  // per-batch j dim = Nn*3

// flash smem layout (halves strides, byte offsets)
#define LDQ 200
#define LDV 72
#define OQH 0
#define OQL 51200
#define OKH 102400
#define OKL 128000
#define OVH 153600
#define OVL 181248
#define SMEM_TOT 208896

// gemm smem layout
#define LDW 72
#define GOWH 0
#define GOWL 18432
#define GOXH 36864
#define GOXL 64512
#define GSMEM 92160

// ---------------- scratch (device globals; no runtime allocation) ----------
__device__ __nv_bfloat16 g_qh[BH * Nn * Ee];
__device__ __nv_bfloat16 g_ql[BH * Nn * Ee];
__device__ __nv_bfloat16 g_kh[BH * Nn * Ee];
__device__ __nv_bfloat16 g_kl[BH * Nn * Ee];
__device__ __nv_bfloat16 g_vh[BH * Ee * Nn];   // [bh][e][n]
__device__ __nv_bfloat16 g_vl[BH * Ee * Nn];
__device__ float         g_ao[BH * Nn * Ee];
__device__ __nv_bfloat16 g_wh[3 * DI * Cc];    // stacked Wq,Wk,Wv [1536][256]
__device__ __nv_bfloat16 g_wl[3 * DI * Cc];
__device__ __nv_bfloat16 g_woh[Cc * DI];       // Wo [256][512]
__device__ __nv_bfloat16 g_wol[Cc * DI];
__device__ __nv_bfloat16 g_xth[Bsz * Jb * Cc]; // xT [b][j][i]
__device__ __nv_bfloat16 g_xtl[Bsz * Jb * Cc];
__device__ __nv_bfloat16 g_aoth[Bsz * Jb * DI];// aoT [b][j][h*64+d]
__device__ __nv_bfloat16 g_aotl[Bsz * Jb * DI];

// ---------------- helpers ---------------------------------------------------
__device__ __forceinline__ uint32_t s2u(const void* p) {
    uint32_t a;
    asm("{ .reg .u64 t; cvta.to.shared.u64 t, %1; cvt.u32.u64 %0, t; }"
        : "=r"(a) : "l"(p));
    return a;
}
__device__ __forceinline__ void ldm4(uint32_t& r0, uint32_t& r1, uint32_t& r2,
                                     uint32_t& r3, uint32_t addr) {
    asm volatile("ldmatrix.sync.aligned.m8n8.x4.shared.b16 {%0,%1,%2,%3}, [%4];"
                 : "=r"(r0), "=r"(r1), "=r"(r2), "=r"(r3) : "r"(addr));
}
__device__ __forceinline__ void mma16816(float* c, const uint32_t* a, const uint32_t* b) {
    asm volatile(
        "mma.sync.aligned.m16n8k16.row.col.f32.bf16.bf16.f32 "
        "{%0,%1,%2,%3},{%4,%5,%6,%7},{%8,%9},{%0,%1,%2,%3};"
        : "+f"(c[0]), "+f"(c[1]), "+f"(c[2]), "+f"(c[3])
        : "r"(a[0]), "r"(a[1]), "r"(a[2]), "r"(a[3]), "r"(b[0]), "r"(b[1]));
}
__device__ __forceinline__ void cpa16(uint32_t dst, const void* src) {
    asm volatile("cp.async.cg.shared.global [%0], [%1], 16;"
                 :: "r"(dst), "l"(src));
}
__device__ __forceinline__ void cpa_wait() {
    asm volatile("cp.async.commit_group;");
    asm volatile("cp.async.wait_group 0;");
}
__device__ __forceinline__ void split_bf16(float x, __nv_bfloat16& h, __nv_bfloat16& l) {
    h = __float2bfloat16(x);
    l = __float2bfloat16(x - __bfloat162float(h));
}
__device__ __forceinline__ uint32_t pack_hi(float a, float b, float& ra, float& rb) {
    __nv_bfloat16 ha = __float2bfloat16(a), hb = __float2bfloat16(b);
    ra = a - __bfloat162float(ha);
    rb = b - __bfloat162float(hb);
    __nv_bfloat162 p(ha, hb);
    return *(uint32_t*)&p;
}
__device__ __forceinline__ uint32_t pack_lo(float ra, float rb) {
    __nv_bfloat162 p(__float2bfloat16(ra), __float2bfloat16(rb));
    return *(uint32_t*)&p;
}

// ---------------------------------------------------------------------------
// prep kernels
// ---------------------------------------------------------------------------
__global__ __launch_bounds__(256)
void split_arr(const float* __restrict__ src, __nv_bfloat16* __restrict__ h,
               __nv_bfloat16* __restrict__ l, int n)
{
    int i = blockIdx.x * 1024 + threadIdx.x;
    #pragma unroll
    for (int s = 0; s < 4; ++s, i += 256)
        if (i < n) {
            __nv_bfloat16 hi, lo;
            split_bf16(src[i], hi, lo);
            h[i] = hi; l[i] = lo;
        }
}

// x (B,N,C,3) -> xT[b][j=n*3+c][i] hi/lo
__global__ __launch_bounds__(256)
void prep_x(const float* __restrict__ x,
            __nv_bfloat16* __restrict__ xh, __nv_bfloat16* __restrict__ xl)
{
    __shared__ float sm[768];
    const int blk = blockIdx.x;              // b*2048 + n
    const int b = blk >> 11, n = blk & 2047;
    const int tid = threadIdx.x;
    const long base = (long)blk * 768;
    #pragma unroll
    for (int s = 0; s < 3; ++s)
        sm[tid + s * 256] = x[base + tid + s * 256];
    __syncthreads();
    #pragma unroll
    for (int s = 0; s < 3; ++s) {
        int c = s, i = tid;
        __nv_bfloat16 hi, lo;
        split_bf16(sm[i * 3 + c], hi, lo);
        long dst = ((long)b * Jb + n * 3 + c) * Cc + i;
        xh[dst] = hi; xl[dst] = lo;
    }
}

// ao [bh][n][e=d*3+c] fp32 -> aoT[b][j=n*3+c][h*64+d] hi/lo
__global__ __launch_bounds__(256)
void prep_ao(const float* __restrict__ ao,
             __nv_bfloat16* __restrict__ h, __nv_bfloat16* __restrict__ l)
{
    __shared__ float sm[4][192];
    const int R0 = blockIdx.x * 4;           // row = bh*2048 + n
    const int tid = threadIdx.x;
    {
        int t = tid;
        for (int s = 0; s < 3; ++s, t += 256)
            sm[t / 192][t % 192] = ao[(long)R0 * 192 + t];
    }
    __syncthreads();
    {
        int t = tid;
        for (int s = 0; s < 3; ++s, t += 256) {
            int row = t / 192, idx = t % 192;
            int c = idx >> 6, d = idx & 63;
            int g = R0 + row;
            int bh = g >> 11, n = g & 2047;
            int b = bh >> 3, hh = bh & 7;
            __nv_bfloat16 hi, lo;
            split_bf16(sm[row][d * 3 + c], hi, lo);
            long dst = ((long)b * Jb + n * 3 + c) * DI + hh * 64 + d;
            h[dst] = hi; l[dst] = lo;
        }
    }
}

// ---------------------------------------------------------------------------
// Shared HMMA-split GEMM mainloop.
// C[128 o x 192 j] = sum_k W[o][k] * X[j][k], 3-product bf16 split.
// wh/wl: ptr at (o row 0); xh/xl: ptr at (j row 0); row stride = ktot.
// ---------------------------------------------------------------------------
__device__ __forceinline__ void gemm_main(
    uint32_t sb, int tid,
    const __nv_bfloat16* __restrict__ wh, const __nv_bfloat16* __restrict__ wl,
    const __nv_bfloat16* __restrict__ xh, const __nv_bfloat16* __restrict__ xl,
    int ktot, float acc[4][6][4])
{
    const int lane = tid & 31, w = tid >> 5;
    const int wm = w >> 2, wn = w & 3;
    const int lrow = lane & 15, lc8 = (lane >> 4) << 3;
    const int nch = ktot >> 6;

    for (int ch = 0; ch < nch; ++ch) {
        const int i0 = ch * 64;
        #pragma unroll
        for (int s = 0; s < 4; ++s) {
            int l = tid + s * 256;
            int row = l >> 3, sg = l & 7;
            uint32_t doff = (uint32_t)(row * LDW + sg * 8) * 2;
            long g = (long)row * ktot + i0 + sg * 8;
            cpa16(sb + GOWH + doff, wh + g);
            cpa16(sb + GOWL + doff, wl + g);
        }
        #pragma unroll
        for (int s = 0; s < 6; ++s) {
            int l = tid + s * 256;
            int row = l >> 3, sg = l & 7;
            uint32_t doff = (uint32_t)(row * LDW + sg * 8) * 2;
            long g = (long)row * ktot + i0 + sg * 8;
            cpa16(sb + GOXH + doff, xh + g);
            cpa16(sb + GOXL + doff, xl + g);
        }
        cpa_wait();
        __syncthreads();

        #pragma unroll
        for (int ks = 0; ks < 4; ++ks) {
            const int kcol = ks * 16 + lc8;
            uint32_t ah_[4][4], al_[4][4];
            #pragma unroll
            for (int mt = 0; mt < 4; ++mt) {
                uint32_t r = (uint32_t)((wm * 64 + mt * 16 + lrow) * LDW + kcol) * 2;
                ldm4(ah_[mt][0], ah_[mt][1], ah_[mt][2], ah_[mt][3], sb + GOWH + r);
                ldm4(al_[mt][0], al_[mt][1], al_[mt][2], al_[mt][3], sb + GOWL + r);
            }
            uint32_t bh_[6][2], bl_[6][2];
            #pragma unroll
            for (int g = 0; g < 3; ++g) {
                uint32_t r = (uint32_t)((wn * 48 + g * 16 + lrow) * LDW + kcol) * 2;
                uint32_t b0, b1, b2, b3;
                ldm4(b0, b1, b2, b3, sb + GOXH + r);
                bh_[2*g][0] = b0; bh_[2*g][1] = b2;
                bh_[2*g+1][0] = b1; bh_[2*g+1][1] = b3;
                ldm4(b0, b1, b2, b3, sb + GOXL + r);
                bl_[2*g][0] = b0; bl_[2*g][1] = b2;
                bl_[2*g+1][0] = b1; bl_[2*g+1][1] = b3;
            }
            #pragma unroll
            for (int mt = 0; mt < 4; ++mt)
                #pragma unroll
                for (int nt = 0; nt < 6; ++nt) {
                    mma16816(acc[mt][nt], ah_[mt], bh_[nt]);
                    mma16816(acc[mt][nt], ah_[mt], bl_[nt]);
                    mma16816(acc[mt][nt], al_[mt], bh_[nt]);
                }
        }
        __syncthreads();
    }
}

// ---------------------------------------------------------------------------
// QKV projection GEMM: grid (64 j-tiles, 12 o-tiles).
// ---------------------------------------------------------------------------
__global__ __launch_bounds__(256, 1)
void qkv_mm(const __nv_bfloat16* __restrict__ wh, const __nv_bfloat16* __restrict__ wl,
            const __nv_bfloat16* __restrict__ xh, const __nv_bfloat16* __restrict__ xl,
            __nv_bfloat16* __restrict__ qh, __nv_bfloat16* __restrict__ ql,
            __nv_bfloat16* __restrict__ kh, __nv_bfloat16* __restrict__ kl,
            __nv_bfloat16* __restrict__ vh, __nv_bfloat16* __restrict__ vl)
{
    extern __shared__ __align__(16) char sm[];
    const uint32_t sb = s2u(sm);
    const int tid = threadIdx.x, lane = tid & 31, w = tid >> 5;
    const int wm = w >> 2, wn = w & 3;
    const int jt = blockIdx.x, ot = blockIdx.y;
    const int b = jt >> 5, o0 = ot * 128;
    const int m = o0 >> 9;                   // 0=q, 1=k, 2=v

    float acc[4][6][4] = {};
    gemm_main(sb, tid,
              wh + (long)o0 * Cc, wl + (long)o0 * Cc,
              xh + ((long)b * Jb + (jt & 31) * 192) * Cc,
              xl + ((long)b * Jb + (jt & 31) * 192) * Cc,
              Cc, acc);

    __nv_bfloat16* oh = (m == 0) ? qh : (m == 1) ? kh : vh;
    __nv_bfloat16* ol = (m == 0) ? ql : (m == 1) ? kl : vl;

    #pragma unroll
    for (int mt = 0; mt < 4; ++mt)
        #pragma unroll
        for (int nt = 0; nt < 6; ++nt)
            #pragma unroll
            for (int e = 0; e < 4; ++e) {
                int rloc = wm * 64 + mt * 16 + (lane >> 2) + ((e >> 1) << 3);
                int cloc = wn * 48 + nt * 8 + (lane & 3) * 2 + (e & 1);
                int o_in = (o0 & 511) + rloc;
                int hh = o_in >> 6, d = o_in & 63;
                int bh = b * 8 + hh;
                int jb = (jt & 31) * 192 + cloc;
                int n = jb / 3, c = jb - 3 * n;
                __nv_bfloat16 hi, lo;
                split_bf16(acc[mt][nt][e], hi, lo);
                long idx;
                if (m < 2) idx = ((long)bh * Nn + n) * Ee + d * 3 + c;
                else       idx = ((long)bh * Ee + d * 3 + c) * Nn + n;
                oh[idx] = hi; ol[idx] = lo;
            }
}

// ---------------------------------------------------------------------------
// Output projection GEMM: grid (64 j-tiles, 2 o-tiles).  fp32 epilogue.
// ---------------------------------------------------------------------------
__global__ __launch_bounds__(256, 1)
void out_mm(const __nv_bfloat16* __restrict__ wh, const __nv_bfloat16* __restrict__ wl,
            const __nv_bfloat16* __restrict__ xh, const __nv_bfloat16* __restrict__ xl,
            float* __restrict__ y)
{
    extern __shared__ __align__(16) char sm[];
    const uint32_t sb = s2u(sm);
    const int tid = threadIdx.x, lane = tid & 31, w = tid >> 5;
    const int wm = w >> 2, wn = w & 3;
    const int jt = blockIdx.x, ot = blockIdx.y;
    const int b = jt >> 5, o0 = ot * 128;

    float acc[4][6][4] = {};
    gemm_main(sb, tid,
              wh + (long)o0 * DI, wl + (long)o0 * DI,
              xh + ((long)b * Jb + (jt & 31) * 192) * DI,
              xl + ((long)b * Jb + (jt & 31) * 192) * DI,
              DI, acc);

    #pragma unroll
    for (int mt = 0; mt < 4; ++mt)
        #pragma unroll
        for (int nt = 0; nt < 6; ++nt)
            #pragma unroll
            for (int e = 0; e < 4; ++e) {
                int rloc = wm * 64 + mt * 16 + (lane >> 2) + ((e >> 1) << 3);
                int cloc = wn * 48 + nt * 8 + (lane & 3) * 2 + (e & 1);
                int o = o0 + rloc;
                int jb = (jt & 31) * 192 + cloc;
                int n = jb / 3, c = jb - 3 * n;
                y[((long)(b * Nn + n) * Cc + o) * 3 + c] = acc[mt][nt][e];
            }
}

// ---------------------------------------------------------------------------
// Fused flash attention (unchanged from round 8 — verified).
// ---------------------------------------------------------------------------
__global__ __launch_bounds__(256, 1)
void vn_flash(const __nv_bfloat16* __restrict__ qh, const __nv_bfloat16* __restrict__ ql,
              const __nv_bfloat16* __restrict__ kh, const __nv_bfloat16* __restrict__ kl,
              const __nv_bfloat16* __restrict__ vh, const __nv_bfloat16* __restrict__ vl,
              float* __restrict__ ao, float scale)
{
    extern __shared__ __align__(16) char sm[];
    const uint32_t sb = s2u(sm);
    const int tid = threadIdx.x, lane = tid & 31, w = tid >> 5;
    const int i0 = blockIdx.x * 128, bh = blockIdx.y;
    const int lrow = lane & 15, lc8 = (lane >> 4) << 3;

    {
        const __nv_bfloat16* Qh = qh + ((long)bh * Nn + i0) * Ee;
        const __nv_bfloat16* Ql = ql + ((long)bh * Nn + i0) * Ee;
        for (int s = tid; s < 128 * 24; s += 256) {
            int row = s / 24, seg = s - row * 24;
            uint32_t doff = (uint32_t)(row * LDQ + seg * 8) * 2;
            long g = (long)row * Ee + seg * 8;
            cpa16(sb + OQH + doff, Qh + g);
            cpa16(sb + OQL + doff, Ql + g);
        }
    }

    float O[24][4];
    #pragma unroll
    for (int i = 0; i < 24; ++i) { O[i][0]=0.f; O[i][1]=0.f; O[i][2]=0.f; O[i][3]=0.f; }
    float m0 = -1e30f, m1 = -1e30f, l0 = 0.f, l1 = 0.f;

    const __nv_bfloat16* Kh = kh + (long)bh * Nn * Ee;
    const __nv_bfloat16* Kl = kl + (long)bh * Nn * Ee;
    const __nv_bfloat16* Vh = vh + (long)bh * Ee * Nn;
    const __nv_bfloat16* Vl = vl + (long)bh * Ee * Nn;

    for (int ch = 0; ch < 32; ++ch) {
        const int jc = ch * 64;
        #pragma unroll
        for (int it = 0; it < 6; ++it) {
            int s = tid + it * 256;
            {
                int row = s / 24, seg = s - row * 24;
                uint32_t doff = (uint32_t)(row * LDQ + seg * 8) * 2;
                long g = (long)(jc + row) * Ee + seg * 8;
                cpa16(sb + OKH + doff, Kh + g);
                cpa16(sb + OKL + doff, Kl + g);
            }
            {
                int row = s >> 3, seg = s & 7;
                uint32_t doff = (uint32_t)(row * LDV + seg * 8) * 2;
                long g = (long)row * Nn + jc + seg * 8;
                cpa16(sb + OVH + doff, Vh + g);
                cpa16(sb + OVL + doff, Vl + g);
            }
        }
        cpa_wait();
        __syncthreads();

        float S[8][4];
        #pragma unroll
        for (int i = 0; i < 8; ++i) { S[i][0]=0.f; S[i][1]=0.f; S[i][2]=0.f; S[i][3]=0.f; }
        #pragma unroll
        for (int ks = 0; ks < 12; ++ks) {
            const int kcol = ks * 16 + lc8;
            uint32_t qah[4], qal[4];
            uint32_t r = (uint32_t)((w * 16 + lrow) * LDQ + kcol) * 2;
            ldm4(qah[0], qah[1], qah[2], qah[3], sb + OQH + r);
            ldm4(qal[0], qal[1], qal[2], qal[3], sb + OQL + r);
            #pragma unroll
            for (int g = 0; g < 4; ++g) {
                uint32_t rb = (uint32_t)((g * 16 + lrow) * LDQ + kcol) * 2;
                uint32_t b0, b1, b2, b3;
                ldm4(b0, b1, b2, b3, sb + OKH + rb);
                uint32_t bh0[2] = {b0, b2}, bh1[2] = {b1, b3};
                ldm4(b0, b1, b2, b3, sb + OKL + rb);
                uint32_t bl0[2] = {b0, b2}, bl1[2] = {b1, b3};
                mma16816(S[2*g],   qah, bh0);
                mma16816(S[2*g],   qah, bl0);
                mma16816(S[2*g],   qal, bh0);
                mma16816(S[2*g+1], qah, bh1);
                mma16816(S[2*g+1], qah, bl1);
                mma16816(S[2*g+1], qal, bh1);
            }
        }

        float pm0 = -1e30f, pm1 = -1e30f;
        #pragma unroll
        for (int nt = 0; nt < 8; ++nt) {
            S[nt][0] *= scale; S[nt][1] *= scale; S[nt][2] *= scale; S[nt][3] *= scale;
            pm0 = fmaxf(pm0, fmaxf(S[nt][0], S[nt][1]));
            pm1 = fmaxf(pm1, fmaxf(S[nt][2], S[nt][3]));
        }
        pm0 = fmaxf(pm0, __shfl_xor_sync(0xffffffffu, pm0, 1));
        pm0 = fmaxf(pm0, __shfl_xor_sync(0xffffffffu, pm0, 2));
        pm1 = fmaxf(pm1, __shfl_xor_sync(0xffffffffu, pm1, 1));
        pm1 = fmaxf(pm1, __shfl_xor_sync(0xffffffffu, pm1, 2));
        const float nm0 = fmaxf(m0, pm0), nm1 = fmaxf(m1, pm1);
        const float a0 = __expf(m0 - nm0), a1 = __expf(m1 - nm1);
        float rs0 = 0.f, rs1 = 0.f;
        #pragma unroll
        for (int nt = 0; nt < 8; ++nt) {
            S[nt][0] = __expf(S[nt][0] - nm0);
            S[nt][1] = __expf(S[nt][1] - nm0);
            S[nt][2] = __expf(S[nt][2] - nm1);
            S[nt][3] = __expf(S[nt][3] - nm1);
            rs0 += S[nt][0] + S[nt][1];
            rs1 += S[nt][2] + S[nt][3];
        }
        rs0 += __shfl_xor_sync(0xffffffffu, rs0, 1);
        rs0 += __shfl_xor_sync(0xffffffffu, rs0, 2);
        rs1 += __shfl_xor_sync(0xffffffffu, rs1, 1);
        rs1 += __shfl_xor_sync(0xffffffffu, rs1, 2);
        l0 = l0 * a0 + rs0;
        l1 = l1 * a1 + rs1;
        m0 = nm0; m1 = nm1;
        #pragma unroll
        for (int nt = 0; nt < 24; ++nt) {
            O[nt][0] *= a0; O[nt][1] *= a0; O[nt][2] *= a1; O[nt][3] *= a1;
        }

        uint32_t pah[4][4], pal[4][4];
        #pragma unroll
        for (int ks = 0; ks < 4; ++ks) {
            const int e2 = 2 * ks, o2 = 2 * ks + 1;
            float ra, rb;
            pah[ks][0] = pack_hi(S[e2][0], S[e2][1], ra, rb); pal[ks][0] = pack_lo(ra, rb);
            pah[ks][1] = pack_hi(S[e2][2], S[e2][3], ra, rb); pal[ks][1] = pack_lo(ra, rb);
            pah[ks][2] = pack_hi(S[o2][0], S[o2][1], ra, rb); pal[ks][2] = pack_lo(ra, rb);
            pah[ks][3] = pack_hi(S[o2][2], S[o2][3], ra, rb); pal[ks][3] = pack_lo(ra, rb);
        }

        #pragma unroll
        for (int ks = 0; ks < 4; ++ks) {
            const int kcol = ks * 16 + lc8;
            #pragma unroll
            for (int gg = 0; gg < 12; ++gg) {
                uint32_t rb = (uint32_t)((gg * 16 + lrow) * LDV + kcol) * 2;
                uint32_t b0, b1, b2, b3;
                ldm4(b0, b1, b2, b3, sb + OVH + rb);
                uint32_t vh0[2] = {b0, b2}, vh1[2] = {b1, b3};
                ldm4(b0, b1, b2, b3, sb + OVL + rb);
                uint32_t vl0[2] = {b0, b2}, vl1[2] = {b1, b3};
                mma16816(O[2*gg],   pah[ks], vh0);
                mma16816(O[2*gg],   pah[ks], vl0);
                mma16816(O[2*gg],   pal[ks], vh0);
                mma16816(O[2*gg+1], pah[ks], vh1);
                mma16816(O[2*gg+1], pah[ks], vl1);
                mma16816(O[2*gg+1], pal[ks], vh1);
            }
        }
        __syncthreads();
    }

    const float inv0 = 1.f / l0, inv1 = 1.f / l1;
    const int rowg = i0 + w * 16 + (lane >> 2);
    const long base = ((long)bh * Nn + rowg) * Ee;
    #pragma unroll
    for (int nt = 0; nt < 24; ++nt) {
        int col = nt * 8 + (lane & 3) * 2;
        *(float2*)(ao + base + col) =
            make_float2(O[nt][0] * inv0, O[nt][1] * inv0);
        *(float2*)(ao + base + 8L * Ee + col) =
            make_float2(O[nt][2] * inv1, O[nt][3] * inv1);
    }
}

// ---------------------------------------------------------------------------
extern "C" void kernel_launch(void* const* d_in, const int* in_sizes, int n_in,
                              void* d_out, int out_size)
{
    const float* x  = (const float*)d_in[0];
    const float* Wq = (const float*)d_in[1];
    const float* Wk = (const float*)d_in[2];
    const float* Wv = (const float*)d_in[3];
    const float* Wo = (const float*)d_in[4];
    float* y = (float*)d_out;

    __nv_bfloat16 *qh, *ql, *kh, *kl, *vh, *vl;
    __nv_bfloat16 *wh, *wl, *woh, *wol, *xth, *xtl, *aoth, *aotl;
    float *ao;
    cudaGetSymbolAddress((void**)&qh,   g_qh);
    cudaGetSymbolAddress((void**)&ql,   g_ql);
    cudaGetSymbolAddress((void**)&kh,   g_kh);
    cudaGetSymbolAddress((void**)&kl,   g_kl);
    cudaGetSymbolAddress((void**)&vh,   g_vh);
    cudaGetSymbolAddress((void**)&vl,   g_vl);
    cudaGetSymbolAddress((void**)&ao,   g_ao);
    cudaGetSymbolAddress((void**)&wh,   g_wh);
    cudaGetSymbolAddress((void**)&wl,   g_wl);
    cudaGetSymbolAddress((void**)&woh,  g_woh);
    cudaGetSymbolAddress((void**)&wol,  g_wol);
    cudaGetSymbolAddress((void**)&xth,  g_xth);
    cudaGetSymbolAddress((void**)&xtl,  g_xtl);
    cudaGetSymbolAddress((void**)&aoth, g_aoth);
    cudaGetSymbolAddress((void**)&aotl, g_aotl);

    cudaFuncSetAttribute(vn_flash, cudaFuncAttributeMaxDynamicSharedMemorySize, SMEM_TOT);
    cudaFuncSetAttribute(qkv_mm,   cudaFuncAttributeMaxDynamicSharedMemorySize, GSMEM);
    cudaFuncSetAttribute(out_mm,   cudaFuncAttributeMaxDynamicSharedMemorySize, GSMEM);

    dim3 blk(256);

    // one-time operand prep (split + transpose)
    const int WN = DI * Cc;                  // 131072
    split_arr<<<(WN + 1023) / 1024, blk>>>(Wq, wh, wl, WN);
    split_arr<<<(WN + 1023) / 1024, blk>>>(Wk, wh + WN, wl + WN, WN);
    split_arr<<<(WN + 1023) / 1024, blk>>>(Wv, wh + 2 * WN, wl + 2 * WN, WN);
    split_arr<<<(WN + 1023) / 1024, blk>>>(Wo, woh, wol, WN);
    prep_x<<<Bsz * Nn, blk>>>(x, xth, xtl);

    // QKV projection (HMMA)
    qkv_mm<<<dim3(64, 12), blk, GSMEM>>>(wh, wl, xth, xtl,
                                         qh, ql, kh, kl, vh, vl);

    // fused attention
    const float scale = 1.0f / sqrtf((float)Ee);
    vn_flash<<<dim3(Nn / 128, BH), blk, SMEM_TOT>>>(qh, ql, kh, kl, vh, vl, ao, scale);

    // out projection (HMMA)
    prep_ao<<<BH * Nn / 4, blk>>>(ao, aoth, aotl);
    out_mm<<<dim3(64, 2), blk, GSMEM>>>(woh, wol, aoth, aotl, y);
}

// round 12
// speedup vs baseline: 1.5409x; 1.0587x over previous
#include <cuda_runtime.h>
#include <cuda_bf16.h>
#include <math.h>
#include <stdint.h>

#define Bsz 2
#define Nn 2048
#define Cc 256
#define COOR 3
#define Hh 8
#define Dd 64
#define Ee 192   // Dd * COOR
#define DI 512   // Hh * Dd
#define BH 16    // Bsz * Hh
#define Jb 6144  // per-batch j dim = Nn*3

// flash smem layout: Q persistent + 2-stage K/V pipeline
#define F_LDQ 200          // Q/K rows: 192 + 8 pad halves (400B)
#define F_LDV 40           // V rows: 32 + 8 pad halves (80B)
#define F_OQH 0
#define F_OQL 51200
#define F_KV0 102400
#define F_STG 56320        // per stage: KH 12800 | KL 12800 | VH 15360 | VL 15360
#define F_SMEM (F_KV0 + 2 * F_STG)   // 215040

// gemm smem layout: 2 stages of (W 128x64 + X 192x64) hi/lo
#define G_LDW 72
#define G_STG 92160        // WH 18432 | WL 18432 | XH 27648 | XL 27648
#define G_SMEM (2 * G_STG) // 184320

// ---------------- scratch (device globals; no runtime allocation) ----------
__device__ __nv_bfloat16 g_qh[BH * Nn * Ee];
__device__ __nv_bfloat16 g_ql[BH * Nn * Ee];
__device__ __nv_bfloat16 g_kh[BH * Nn * Ee];
__device__ __nv_bfloat16 g_kl[BH * Nn * Ee];
__device__ __nv_bfloat16 g_vh[BH * Ee * Nn];   // [bh][e][n]
__device__ __nv_bfloat16 g_vl[BH * Ee * Nn];
__device__ float         g_ao[BH * Nn * Ee];
__device__ __nv_bfloat16 g_wh[3 * DI * Cc];    // stacked Wq,Wk,Wv [1536][256]
__device__ __nv_bfloat16 g_wl[3 * DI * Cc];
__device__ __nv_bfloat16 g_woh[Cc * DI];       // Wo [256][512]
__device__ __nv_bfloat16 g_wol[Cc * DI];
__device__ __nv_bfloat16 g_xth[Bsz * Jb * Cc]; // xT [b][j][i]
__device__ __nv_bfloat16 g_xtl[Bsz * Jb * Cc];
__device__ __nv_bfloat16 g_aoth[Bsz * Jb * DI];// aoT [b][j][h*64+d]
__device__ __nv_bfloat16 g_aotl[Bsz * Jb * DI];

// ---------------- helpers ---------------------------------------------------
__device__ __forceinline__ uint32_t s2u(const void* p) {
    uint32_t a;
    asm("{ .reg .u64 t; cvta.to.shared.u64 t, %1; cvt.u32.u64 %0, t; }"
        : "=r"(a) : "l"(p));
    return a;
}
__device__ __forceinline__ void ldm4(uint32_t& r0, uint32_t& r1, uint32_t& r2,
                                     uint32_t& r3, uint32_t addr) {
    asm volatile("ldmatrix.sync.aligned.m8n8.x4.shared.b16 {%0,%1,%2,%3}, [%4];"
                 : "=r"(r0), "=r"(r1), "=r"(r2), "=r"(r3) : "r"(addr));
}
__device__ __forceinline__ void mma16816(float* c, const uint32_t* a, const uint32_t* b) {
    asm volatile(
        "mma.sync.aligned.m16n8k16.row.col.f32.bf16.bf16.f32 "
        "{%0,%1,%2,%3},{%4,%5,%6,%7},{%8,%9},{%0,%1,%2,%3};"
        : "+f"(c[0]), "+f"(c[1]), "+f"(c[2]), "+f"(c[3])
        : "r"(a[0]), "r"(a[1]), "r"(a[2]), "r"(a[3]), "r"(b[0]), "r"(b[1]));
}
__device__ __forceinline__ void cpa16(uint32_t dst, const void* src) {
    asm volatile("cp.async.cg.shared.global [%0], [%1], 16;"
                 :: "r"(dst), "l"(src));
}
__device__ __forceinline__ void cpa_commit() {
    asm volatile("cp.async.commit_group;");
}
__device__ __forceinline__ void cpa_wait0() {
    asm volatile("cp.async.wait_group 0;");
}
__device__ __forceinline__ void cpa_wait1() {
    asm volatile("cp.async.wait_group 1;");
}
__device__ __forceinline__ void split_bf16(float x, __nv_bfloat16& h, __nv_bfloat16& l) {
    h = __float2bfloat16(x);
    l = __float2bfloat16(x - __bfloat162float(h));
}
__device__ __forceinline__ uint32_t pack_hi(float a, float b, float& ra, float& rb) {
    __nv_bfloat16 ha = __float2bfloat16(a), hb = __float2bfloat16(b);
    ra = a - __bfloat162float(ha);
    rb = b - __bfloat162float(hb);
    __nv_bfloat162 p(ha, hb);
    return *(uint32_t*)&p;
}
__device__ __forceinline__ uint32_t pack_lo(float ra, float rb) {
    __nv_bfloat162 p(__float2bfloat16(ra), __float2bfloat16(rb));
    return *(uint32_t*)&p;
}

// ---------------------------------------------------------------------------
// prep kernels
// ---------------------------------------------------------------------------
__global__ __launch_bounds__(256)
void split_arr(const float* __restrict__ src, __nv_bfloat16* __restrict__ h,
               __nv_bfloat16* __restrict__ l, int n)
{
    int i = blockIdx.x * 1024 + threadIdx.x;
    #pragma unroll
    for (int s = 0; s < 4; ++s, i += 256)
        if (i < n) {
            __nv_bfloat16 hi, lo;
            split_bf16(src[i], hi, lo);
            h[i] = hi; l[i] = lo;
        }
}

__global__ __launch_bounds__(256)
void prep_x(const float* __restrict__ x,
            __nv_bfloat16* __restrict__ xh, __nv_bfloat16* __restrict__ xl)
{
    __shared__ float sm[768];
    const int blk = blockIdx.x;
    const int b = blk >> 11, n = blk & 2047;
    const int tid = threadIdx.x;
    const long base = (long)blk * 768;
    #pragma unroll
    for (int s = 0; s < 3; ++s)
        sm[tid + s * 256] = x[base + tid + s * 256];
    __syncthreads();
    #pragma unroll
    for (int s = 0; s < 3; ++s) {
        int c = s, i = tid;
        __nv_bfloat16 hi, lo;
        split_bf16(sm[i * 3 + c], hi, lo);
        long dst = ((long)b * Jb + n * 3 + c) * Cc + i;
        xh[dst] = hi; xl[dst] = lo;
    }
}

__global__ __launch_bounds__(256)
void prep_ao(const float* __restrict__ ao,
             __nv_bfloat16* __restrict__ h, __nv_bfloat16* __restrict__ l)
{
    __shared__ float sm[4][192];
    const int R0 = blockIdx.x * 4;
    const int tid = threadIdx.x;
    {
        int t = tid;
        for (int s = 0; s < 3; ++s, t += 256)
            sm[t / 192][t % 192] = ao[(long)R0 * 192 + t];
    }
    __syncthreads();
    {
        int t = tid;
        for (int s = 0; s < 3; ++s, t += 256) {
            int row = t / 192, idx = t % 192;
            int c = idx >> 6, d = idx & 63;
            int g = R0 + row;
            int bh = g >> 11, n = g & 2047;
            int b = bh >> 3, hh = bh & 7;
            __nv_bfloat16 hi, lo;
            split_bf16(sm[row][d * 3 + c], hi, lo);
            long dst = ((long)b * Jb + n * 3 + c) * DI + hh * 64 + d;
            h[dst] = hi; l[dst] = lo;
        }
    }
}

// ---------------------------------------------------------------------------
// GEMM mainloop, 2-stage pipelined.
// ---------------------------------------------------------------------------
__device__ __forceinline__ void gemm_issue(
    uint32_t sb, int tid, int stage, int i0,
    const __nv_bfloat16* __restrict__ wh, const __nv_bfloat16* __restrict__ wl,
    const __nv_bfloat16* __restrict__ xh, const __nv_bfloat16* __restrict__ xl,
    int ktot)
{
    const uint32_t b0 = sb + stage * G_STG;
    #pragma unroll
    for (int s = 0; s < 4; ++s) {
        int l = tid + s * 256;
        int row = l >> 3, sg = l & 7;
        uint32_t doff = (uint32_t)(row * G_LDW + sg * 8) * 2;
        long g = (long)row * ktot + i0 + sg * 8;
        cpa16(b0 + doff, wh + g);
        cpa16(b0 + 18432 + doff, wl + g);
    }
    #pragma unroll
    for (int s = 0; s < 6; ++s) {
        int l = tid + s * 256;
        int row = l >> 3, sg = l & 7;
        uint32_t doff = (uint32_t)(row * G_LDW + sg * 8) * 2;
        long g = (long)row * ktot + i0 + sg * 8;
        cpa16(b0 + 36864 + doff, xh + g);
        cpa16(b0 + 64512 + doff, xl + g);
    }
}

__device__ __forceinline__ void gemm_main(
    uint32_t sb, int tid,
    const __nv_bfloat16* __restrict__ wh, const __nv_bfloat16* __restrict__ wl,
    const __nv_bfloat16* __restrict__ xh, const __nv_bfloat16* __restrict__ xl,
    int ktot, float acc[4][6][4])
{
    const int lane = tid & 31, w = tid >> 5;
    const int wm = w >> 2, wn = w & 3;
    const int lrow = lane & 15, lc8 = (lane >> 4) << 3;
    const int nch = ktot >> 6;

    gemm_issue(sb, tid, 0, 0, wh, wl, xh, xl, ktot);
    cpa_commit();

    for (int ch = 0; ch < nch; ++ch) {
        if (ch + 1 < nch) {
            gemm_issue(sb, tid, (ch + 1) & 1, (ch + 1) * 64, wh, wl, xh, xl, ktot);
            cpa_commit();
            cpa_wait1();
        } else {
            cpa_wait0();
        }
        __syncthreads();

        const uint32_t b0 = sb + (ch & 1) * G_STG;
        #pragma unroll
        for (int ks = 0; ks < 4; ++ks) {
            const int kcol = ks * 16 + lc8;
            uint32_t ah_[4][4], al_[4][4];
            #pragma unroll
            for (int mt = 0; mt < 4; ++mt) {
                uint32_t r = (uint32_t)((wm * 64 + mt * 16 + lrow) * G_LDW + kcol) * 2;
                ldm4(ah_[mt][0], ah_[mt][1], ah_[mt][2], ah_[mt][3], b0 + r);
                ldm4(al_[mt][0], al_[mt][1], al_[mt][2], al_[mt][3], b0 + 18432 + r);
            }
            uint32_t bh_[6][2], bl_[6][2];
            #pragma unroll
            for (int g = 0; g < 3; ++g) {
                uint32_t r = (uint32_t)((wn * 48 + g * 16 + lrow) * G_LDW + kcol) * 2;
                uint32_t b0r, b1r, b2r, b3r;
                ldm4(b0r, b1r, b2r, b3r, b0 + 36864 + r);
                bh_[2*g][0] = b0r; bh_[2*g][1] = b2r;
                bh_[2*g+1][0] = b1r; bh_[2*g+1][1] = b3r;
                ldm4(b0r, b1r, b2r, b3r, b0 + 64512 + r);
                bl_[2*g][0] = b0r; bl_[2*g][1] = b2r;
                bl_[2*g+1][0] = b1r; bl_[2*g+1][1] = b3r;
            }
            #pragma unroll
            for (int mt = 0; mt < 4; ++mt)
                #pragma unroll
                for (int nt = 0; nt < 6; ++nt) {
                    mma16816(acc[mt][nt], ah_[mt], bh_[nt]);
                    mma16816(acc[mt][nt], ah_[mt], bl_[nt]);
                    mma16816(acc[mt][nt], al_[mt], bh_[nt]);
                }
        }
        __syncthreads();
    }
}

// ---------------------------------------------------------------------------
// QKV projection GEMM
// ---------------------------------------------------------------------------
__global__ __launch_bounds__(256, 1)
void qkv_mm(const __nv_bfloat16* __restrict__ wh, const __nv_bfloat16* __restrict__ wl,
            const __nv_bfloat16* __restrict__ xh, const __nv_bfloat16* __restrict__ xl,
            __nv_bfloat16* __restrict__ qh, __nv_bfloat16* __restrict__ ql,
            __nv_bfloat16* __restrict__ kh, __nv_bfloat16* __restrict__ kl,
            __nv_bfloat16* __restrict__ vh, __nv_bfloat16* __restrict__ vl)
{
    extern __shared__ __align__(16) char sm[];
    const uint32_t sb = s2u(sm);
    const int tid = threadIdx.x, lane = tid & 31, w = tid >> 5;
    const int wm = w >> 2, wn = w & 3;
    const int jt = blockIdx.x, ot = blockIdx.y;
    const int b = jt >> 5, o0 = ot * 128;
    const int m = o0 >> 9;

    float acc[4][6][4] = {};
    gemm_main(sb, tid,
              wh + (long)o0 * Cc, wl + (long)o0 * Cc,
              xh + ((long)b * Jb + (jt & 31) * 192) * Cc,
              xl + ((long)b * Jb + (jt & 31) * 192) * Cc,
              Cc, acc);

    __nv_bfloat16* oh = (m == 0) ? qh : (m == 1) ? kh : vh;
    __nv_bfloat16* ol = (m == 0) ? ql : (m == 1) ? kl : vl;

    #pragma unroll
    for (int mt = 0; mt < 4; ++mt)
        #pragma unroll
        for (int nt = 0; nt < 6; ++nt)
            #pragma unroll
            for (int e = 0; e < 4; ++e) {
                int rloc = wm * 64 + mt * 16 + (lane >> 2) + ((e >> 1) << 3);
                int cloc = wn * 48 + nt * 8 + (lane & 3) * 2 + (e & 1);
                int o_in = (o0 & 511) + rloc;
                int hh = o_in >> 6, d = o_in & 63;
                int bh = b * 8 + hh;
                int jb = (jt & 31) * 192 + cloc;
                int n = jb / 3, c = jb - 3 * n;
                __nv_bfloat16 hi, lo;
                split_bf16(acc[mt][nt][e], hi, lo);
                long idx;
                if (m < 2) idx = ((long)bh * Nn + n) * Ee + d * 3 + c;
                else       idx = ((long)bh * Ee + d * 3 + c) * Nn + n;
                oh[idx] = hi; ol[idx] = lo;
            }
}

// ---------------------------------------------------------------------------
// Output projection GEMM
// ---------------------------------------------------------------------------
__global__ __launch_bounds__(256, 1)
void out_mm(const __nv_bfloat16* __restrict__ wh, const __nv_bfloat16* __restrict__ wl,
            const __nv_bfloat16* __restrict__ xh, const __nv_bfloat16* __restrict__ xl,
            float* __restrict__ y)
{
    extern __shared__ __align__(16) char sm[];
    const uint32_t sb = s2u(sm);
    const int tid = threadIdx.x, lane = tid & 31, w = tid >> 5;
    const int wm = w >> 2, wn = w & 3;
    const int jt = blockIdx.x, ot = blockIdx.y;
    const int b = jt >> 5, o0 = ot * 128;

    float acc[4][6][4] = {};
    gemm_main(sb, tid,
              wh + (long)o0 * DI, wl + (long)o0 * DI,
              xh + ((long)b * Jb + (jt & 31) * 192) * DI,
              xl + ((long)b * Jb + (jt & 31) * 192) * DI,
              DI, acc);

    #pragma unroll
    for (int mt = 0; mt < 4; ++mt)
        #pragma unroll
        for (int nt = 0; nt < 6; ++nt)
            #pragma unroll
            for (int e = 0; e < 4; ++e) {
                int rloc = wm * 64 + mt * 16 + (lane >> 2) + ((e >> 1) << 3);
                int cloc = wn * 48 + nt * 8 + (lane & 3) * 2 + (e & 1);
                int o = o0 + rloc;
                int jb = (jt & 31) * 192 + cloc;
                int n = jb / 3, c = jb - 3 * n;
                y[((long)(b * Nn + n) * Cc + o) * 3 + c] = acc[mt][nt][e];
            }
}

// ---------------------------------------------------------------------------
// Fused flash attention, 2-stage pipelined K/V, j-chunk 32.
// ---------------------------------------------------------------------------
__device__ __forceinline__ void flash_issue(
    uint32_t sb, int tid, int jc, int stage,
    const __nv_bfloat16* __restrict__ Kh, const __nv_bfloat16* __restrict__ Kl,
    const __nv_bfloat16* __restrict__ Vh, const __nv_bfloat16* __restrict__ Vl)
{
    const uint32_t kb = sb + F_KV0 + stage * F_STG;
    #pragma unroll
    for (int it = 0; it < 3; ++it) {
        int s = tid + it * 256;
        int row = s / 24, seg = s - row * 24;          // K: 32 rows x 24 segs
        uint32_t doff = (uint32_t)(row * F_LDQ + seg * 8) * 2;
        long g = (long)(jc + row) * Ee + seg * 8;
        cpa16(kb + doff, Kh + g);
        cpa16(kb + 12800 + doff, Kl + g);
    }
    #pragma unroll
    for (int it = 0; it < 3; ++it) {
        int s = tid + it * 256;
        int row = s >> 2, seg = s & 3;                 // V: 192 rows x 4 segs
        uint32_t doff = (uint32_t)(row * F_LDV + seg * 8) * 2;
        long g = (long)row * Nn + jc + seg * 8;
        cpa16(kb + 25600 + doff, Vh + g);
        cpa16(kb + 40960 + doff, Vl + g);
    }
}

__global__ __launch_bounds__(256, 1)
void vn_flash(const __nv_bfloat16* __restrict__ qh, const __nv_bfloat16* __restrict__ ql,
              const __nv_bfloat16* __restrict__ kh, const __nv_bfloat16* __restrict__ kl,
              const __nv_bfloat16* __restrict__ vh, const __nv_bfloat16* __restrict__ vl,
              float* __restrict__ ao, float scale)
{
    extern __shared__ __align__(16) char sm[];
    const uint32_t sb = s2u(sm);
    const int tid = threadIdx.x, lane = tid & 31, w = tid >> 5;
    const int i0 = blockIdx.x * 128, bh = blockIdx.y;
    const int lrow = lane & 15, lc8 = (lane >> 4) << 3;

    const __nv_bfloat16* Kh = kh + (long)bh * Nn * Ee;
    const __nv_bfloat16* Kl = kl + (long)bh * Nn * Ee;
    const __nv_bfloat16* Vh = vh + (long)bh * Ee * Nn;
    const __nv_bfloat16* Vl = vl + (long)bh * Ee * Nn;

    // stage Q (128 x 192 hi/lo) + first K/V chunk, one commit group
    {
        const __nv_bfloat16* Qh = qh + ((long)bh * Nn + i0) * Ee;
        const __nv_bfloat16* Ql = ql + ((long)bh * Nn + i0) * Ee;
        for (int s = tid; s < 128 * 24; s += 256) {
            int row = s / 24, seg = s - row * 24;
            uint32_t doff = (uint32_t)(row * F_LDQ + seg * 8) * 2;
            long g = (long)row * Ee + seg * 8;
            cpa16(sb + F_OQH + doff, Qh + g);
            cpa16(sb + F_OQL + doff, Ql + g);
        }
    }
    flash_issue(sb, tid, 0, 0, Kh, Kl, Vh, Vl);
    cpa_commit();

    float O[24][4];
    #pragma unroll
    for (int i = 0; i < 24; ++i) { O[i][0]=0.f; O[i][1]=0.f; O[i][2]=0.f; O[i][3]=0.f; }
    float m0 = -1e30f, m1 = -1e30f, l0 = 0.f, l1 = 0.f;

    for (int ch = 0; ch < 64; ++ch) {
        if (ch < 63) {
            flash_issue(sb, tid, (ch + 1) * 32, (ch + 1) & 1, Kh, Kl, Vh, Vl);
            cpa_commit();
            cpa_wait1();
        } else {
            cpa_wait0();
        }
        __syncthreads();

        const uint32_t kb = sb + F_KV0 + (ch & 1) * F_STG;

        // ---- S = q k^T  (16 rows x 32 cols per warp) ----
        float S[4][4];
        #pragma unroll
        for (int i = 0; i < 4; ++i) { S[i][0]=0.f; S[i][1]=0.f; S[i][2]=0.f; S[i][3]=0.f; }
        #pragma unroll
        for (int ks = 0; ks < 12; ++ks) {
            const int kcol = ks * 16 + lc8;
            uint32_t qah[4], qal[4];
            uint32_t r = (uint32_t)((w * 16 + lrow) * F_LDQ + kcol) * 2;
            ldm4(qah[0], qah[1], qah[2], qah[3], sb + F_OQH + r);
            ldm4(qal[0], qal[1], qal[2], qal[3], sb + F_OQL + r);
            #pragma unroll
            for (int g = 0; g < 2; ++g) {
                uint32_t rb = (uint32_t)((g * 16 + lrow) * F_LDQ + kcol) * 2;
                uint32_t b0, b1, b2, b3;
                ldm4(b0, b1, b2, b3, kb + rb);
                uint32_t bh0[2] = {b0, b2}, bh1[2] = {b1, b3};
                ldm4(b0, b1, b2, b3, kb + 12800 + rb);
                uint32_t bl0[2] = {b0, b2}, bl1[2] = {b1, b3};
                mma16816(S[2*g],   qah, bh0);
                mma16816(S[2*g],   qah, bl0);
                mma16816(S[2*g],   qal, bh0);
                mma16816(S[2*g+1], qah, bh1);
                mma16816(S[2*g+1], qah, bl1);
                mma16816(S[2*g+1], qal, bh1);
            }
        }

        // ---- online softmax ----
        float pm0 = -1e30f, pm1 = -1e30f;
        #pragma unroll
        for (int nt = 0; nt < 4; ++nt) {
            S[nt][0] *= scale; S[nt][1] *= scale; S[nt][2] *= scale; S[nt][3] *= scale;
            pm0 = fmaxf(pm0, fmaxf(S[nt][0], S[nt][1]));
            pm1 = fmaxf(pm1, fmaxf(S[nt][2], S[nt][3]));
        }
        pm0 = fmaxf(pm0, __shfl_xor_sync(0xffffffffu, pm0, 1));
        pm0 = fmaxf(pm0, __shfl_xor_sync(0xffffffffu, pm0, 2));
        pm1 = fmaxf(pm1, __shfl_xor_sync(0xffffffffu, pm1, 1));
        pm1 = fmaxf(pm1, __shfl_xor_sync(0xffffffffu, pm1, 2));
        const float nm0 = fmaxf(m0, pm0), nm1 = fmaxf(m1, pm1);
        const float a0 = __expf(m0 - nm0), a1 = __expf(m1 - nm1);
        float rs0 = 0.f, rs1 = 0.f;
        #pragma unroll
        for (int nt = 0; nt < 4; ++nt) {
            S[nt][0] = __expf(S[nt][0] - nm0);
            S[nt][1] = __expf(S[nt][1] - nm0);
            S[nt][2] = __expf(S[nt][2] - nm1);
            S[nt][3] = __expf(S[nt][3] - nm1);
            rs0 += S[nt][0] + S[nt][1];
            rs1 += S[nt][2] + S[nt][3];
        }
        rs0 += __shfl_xor_sync(0xffffffffu, rs0, 1);
        rs0 += __shfl_xor_sync(0xffffffffu, rs0, 2);
        rs1 += __shfl_xor_sync(0xffffffffu, rs1, 1);
        rs1 += __shfl_xor_sync(0xffffffffu, rs1, 2);
        l0 = l0 * a0 + rs0;
        l1 = l1 * a1 + rs1;
        m0 = nm0; m1 = nm1;
        #pragma unroll
        for (int nt = 0; nt < 24; ++nt) {
            O[nt][0] *= a0; O[nt][1] *= a0; O[nt][2] *= a1; O[nt][3] *= a1;
        }

        // ---- pack P (C-frag -> A-frag identity) ----
        uint32_t pah[2][4], pal[2][4];
        #pragma unroll
        for (int ks = 0; ks < 2; ++ks) {
            const int e2 = 2 * ks, o2 = 2 * ks + 1;
            float ra, rb;
            pah[ks][0] = pack_hi(S[e2][0], S[e2][1], ra, rb); pal[ks][0] = pack_lo(ra, rb);
            pah[ks][1] = pack_hi(S[e2][2], S[e2][3], ra, rb); pal[ks][1] = pack_lo(ra, rb);
            pah[ks][2] = pack_hi(S[o2][0], S[o2][1], ra, rb); pal[ks][2] = pack_lo(ra, rb);
            pah[ks][3] = pack_hi(S[o2][2], S[o2][3], ra, rb); pal[ks][3] = pack_lo(ra, rb);
        }

        // ---- O += P @ V ----
        #pragma unroll
        for (int ks = 0; ks < 2; ++ks) {
            const int kcol = ks * 16 + lc8;
            #pragma unroll
            for (int gg = 0; gg < 12; ++gg) {
                uint32_t rb = (uint32_t)((gg * 16 + lrow) * F_LDV + kcol) * 2;
                uint32_t b0, b1, b2, b3;
                ldm4(b0, b1, b2, b3, kb + 25600 + rb);
                uint32_t vh0[2] = {b0, b2}, vh1[2] = {b1, b3};
                ldm4(b0, b1, b2, b3, kb + 40960 + rb);
                uint32_t vl0[2] = {b0, b2}, vl1[2] = {b1, b3};
                mma16816(O[2*gg],   pah[ks], vh0);
                mma16816(O[2*gg],   pah[ks], vl0);
                mma16816(O[2*gg],   pal[ks], vh0);
                mma16816(O[2*gg+1], pah[ks], vh1);
                mma16816(O[2*gg+1], pah[ks], vl1);
                mma16816(O[2*gg+1], pal[ks], vh1);
            }
        }
        __syncthreads();
    }

    // ---- epilogue ----
    const float inv0 = 1.f / l0, inv1 = 1.f / l1;
    const int rowg = i0 + w * 16 + (lane >> 2);
    const long base = ((long)bh * Nn + rowg) * Ee;
    #pragma unroll
    for (int nt = 0; nt < 24; ++nt) {
        int col = nt * 8 + (lane & 3) * 2;
        *(float2*)(ao + base + col) =
            make_float2(O[nt][0] * inv0, O[nt][1] * inv0);
        *(float2*)(ao + base + 8L * Ee + col) =
            make_float2(O[nt][2] * inv1, O[nt][3] * inv1);
    }
}

// ---------------------------------------------------------------------------
extern "C" void kernel_launch(void* const* d_in, const int* in_sizes, int n_in,
                              void* d_out, int out_size)
{
    const float* x  = (const float*)d_in[0];
    const float* Wq = (const float*)d_in[1];
    const float* Wk = (const float*)d_in[2];
    const float* Wv = (const float*)d_in[3];
    const float* Wo = (const float*)d_in[4];
    float* y = (float*)d_out;

    __nv_bfloat16 *qh, *ql, *kh, *kl, *vh, *vl;
    __nv_bfloat16 *wh, *wl, *woh, *wol, *xth, *xtl, *aoth, *aotl;
    float *ao;
    cudaGetSymbolAddress((void**)&qh,   g_qh);
    cudaGetSymbolAddress((void**)&ql,   g_ql);
    cudaGetSymbolAddress((void**)&kh,   g_kh);
    cudaGetSymbolAddress((void**)&kl,   g_kl);
    cudaGetSymbolAddress((void**)&vh,   g_vh);
    cudaGetSymbolAddress((void**)&vl,   g_vl);
    cudaGetSymbolAddress((void**)&ao,   g_ao);
    cudaGetSymbolAddress((void**)&wh,   g_wh);
    cudaGetSymbolAddress((void**)&wl,   g_wl);
    cudaGetSymbolAddress((void**)&woh,  g_woh);
    cudaGetSymbolAddress((void**)&wol,  g_wol);
    cudaGetSymbolAddress((void**)&xth,  g_xth);
    cudaGetSymbolAddress((void**)&xtl,  g_xtl);
    cudaGetSymbolAddress((void**)&aoth, g_aoth);
    cudaGetSymbolAddress((void**)&aotl, g_aotl);

    cudaFuncSetAttribute(vn_flash, cudaFuncAttributeMaxDynamicSharedMemorySize, F_SMEM);
    cudaFuncSetAttribute(qkv_mm,   cudaFuncAttributeMaxDynamicSharedMemorySize, G_SMEM);
    cudaFuncSetAttribute(out_mm,   cudaFuncAttributeMaxDynamicSharedMemorySize, G_SMEM);

    dim3 blk(256);

    const int WN = DI * Cc;
    split_arr<<<(WN + 1023) / 1024, blk>>>(Wq, wh, wl, WN);
    split_arr<<<(WN + 1023) / 1024, blk>>>(Wk, wh + WN, wl + WN, WN);
    split_arr<<<(WN + 1023) / 1024, blk>>>(Wv, wh + 2 * WN, wl + 2 * WN, WN);
    split_arr<<<(WN + 1023) / 1024, blk>>>(Wo, woh, wol, WN);
    prep_x<<<Bsz * Nn, blk>>>(x, xth, xtl);

    qkv_mm<<<dim3(64, 12), blk, G_SMEM>>>(wh, wl, xth, xtl,
                                          qh, ql, kh, kl, vh, vl);

    const float scale = 1.0f / sqrtf((float)Ee);
    vn_flash<<<dim3(Nn / 128, BH), blk, F_SMEM>>>(qh, ql, kh, kl, vh, vl, ao, scale);

    prep_ao<<<BH * Nn / 4, blk>>>(ao, aoth, aotl);
    out_mm<<<dim3(64, 2), blk, G_SMEM>>>(woh, wol, aoth, aotl, y);
}

// round 13
// speedup vs baseline: 1.8773x; 1.2183x over previous
#include <cuda_runtime.h>
#include <cuda_fp16.h>
#include <math.h>
#include <stdint.h>

#define Bsz 2
#define Nn 2048
#define Cc 256
#define COOR 3
#define Hh 8
#define Dd 64
#define Ee 192   // Dd * COOR
#define DI 512   // Hh * Dd
#define BH 16    // Bsz * Hh
#define Jb 6144  // per-batch j dim = Nn*3

// flash smem: Q hi/lo persistent + 2-stage (K hi | V hi | V lo)
#define F_LDQ 200          // Q/K rows: 192 + 8 pad halves (400B)
#define F_LDV 40           // V rows: 32 + 8 pad halves (80B)
#define F_OQH 0
#define F_OQL 51200
#define F_KV0 102400
#define F_STG 43520        // KH 12800 | VH 15360 | VL 15360
#define F_SMEM (F_KV0 + 2 * F_STG)   // 189440

// gemm smem: 2 stages of (W 128x64 + X 192x64) hi/lo
#define G_LDW 72
#define G_STG 92160        // WH 18432 | WL 18432 | XH 27648 | XL 27648
#define G_SMEM (2 * G_STG) // 184320

// ---------------- scratch (device globals; no runtime allocation) ----------
__device__ __half g_qh[BH * Nn * Ee];
__device__ __half g_ql[BH * Nn * Ee];
__device__ __half g_kh[BH * Nn * Ee];
__device__ __half g_kl[BH * Nn * Ee];
__device__ __half g_vh[BH * Ee * Nn];   // [bh][e][n]
__device__ __half g_vl[BH * Ee * Nn];
__device__ float  g_ao[BH * Nn * Ee];
__device__ __half g_wh[3 * DI * Cc];    // stacked Wq,Wk,Wv [1536][256]
__device__ __half g_wl[3 * DI * Cc];
__device__ __half g_woh[Cc * DI];       // Wo [256][512]
__device__ __half g_wol[Cc * DI];
__device__ __half g_xth[Bsz * Jb * Cc]; // xT [b][j][i]
__device__ __half g_xtl[Bsz * Jb * Cc];
__device__ __half g_aoth[Bsz * Jb * DI];// aoT [b][j][h*64+d]
__device__ __half g_aotl[Bsz * Jb * DI];

// ---------------- helpers ---------------------------------------------------
__device__ __forceinline__ uint32_t s2u(const void* p) {
    uint32_t a;
    asm("{ .reg .u64 t; cvta.to.shared.u64 t, %1; cvt.u32.u64 %0, t; }"
        : "=r"(a) : "l"(p));
    return a;
}
__device__ __forceinline__ void ldm4(uint32_t& r0, uint32_t& r1, uint32_t& r2,
                                     uint32_t& r3, uint32_t addr) {
    asm volatile("ldmatrix.sync.aligned.m8n8.x4.shared.b16 {%0,%1,%2,%3}, [%4];"
                 : "=r"(r0), "=r"(r1), "=r"(r2), "=r"(r3) : "r"(addr));
}
__device__ __forceinline__ void mma16816(float* c, const uint32_t* a, const uint32_t* b) {
    asm volatile(
        "mma.sync.aligned.m16n8k16.row.col.f32.f16.f16.f32 "
        "{%0,%1,%2,%3},{%4,%5,%6,%7},{%8,%9},{%0,%1,%2,%3};"
        : "+f"(c[0]), "+f"(c[1]), "+f"(c[2]), "+f"(c[3])
        : "r"(a[0]), "r"(a[1]), "r"(a[2]), "r"(a[3]), "r"(b[0]), "r"(b[1]));
}
__device__ __forceinline__ void cpa16(uint32_t dst, const void* src) {
    asm volatile("cp.async.cg.shared.global [%0], [%1], 16;"
                 :: "r"(dst), "l"(src));
}
__device__ __forceinline__ void cpa_commit() {
    asm volatile("cp.async.commit_group;");
}
__device__ __forceinline__ void cpa_wait0() {
    asm volatile("cp.async.wait_group 0;");
}
__device__ __forceinline__ void cpa_wait1() {
    asm volatile("cp.async.wait_group 1;");
}
__device__ __forceinline__ void split_f16(float x, __half& h, __half& l) {
    h = __float2half(x);
    l = __float2half(x - __half2float(h));
}
__device__ __forceinline__ uint32_t pack_f16x2(float a, float b) {
    __half2 p = __halves2half2(__float2half(a), __float2half(b));
    return *(uint32_t*)&p;
}

// ---------------------------------------------------------------------------
// prep kernels
// ---------------------------------------------------------------------------
__global__ __launch_bounds__(256)
void split_arr(const float* __restrict__ src, __half* __restrict__ h,
               __half* __restrict__ l, int n)
{
    int i = blockIdx.x * 1024 + threadIdx.x;
    #pragma unroll
    for (int s = 0; s < 4; ++s, i += 256)
        if (i < n) {
            __half hi, lo;
            split_f16(src[i], hi, lo);
            h[i] = hi; l[i] = lo;
        }
}

__global__ __launch_bounds__(256)
void prep_x(const float* __restrict__ x,
            __half* __restrict__ xh, __half* __restrict__ xl)
{
    __shared__ float sm[768];
    const int blk = blockIdx.x;
    const int b = blk >> 11, n = blk & 2047;
    const int tid = threadIdx.x;
    const long base = (long)blk * 768;
    #pragma unroll
    for (int s = 0; s < 3; ++s)
        sm[tid + s * 256] = x[base + tid + s * 256];
    __syncthreads();
    #pragma unroll
    for (int s = 0; s < 3; ++s) {
        int c = s, i = tid;
        __half hi, lo;
        split_f16(sm[i * 3 + c], hi, lo);
        long dst = ((long)b * Jb + n * 3 + c) * Cc + i;
        xh[dst] = hi; xl[dst] = lo;
    }
}

__global__ __launch_bounds__(256)
void prep_ao(const float* __restrict__ ao,
             __half* __restrict__ h, __half* __restrict__ l)
{
    __shared__ float sm[4][192];
    const int R0 = blockIdx.x * 4;
    const int tid = threadIdx.x;
    {
        int t = tid;
        for (int s = 0; s < 3; ++s, t += 256)
            sm[t / 192][t % 192] = ao[(long)R0 * 192 + t];
    }
    __syncthreads();
    {
        int t = tid;
        for (int s = 0; s < 3; ++s, t += 256) {
            int row = t / 192, idx = t % 192;
            int c = idx >> 6, d = idx & 63;
            int g = R0 + row;
            int bh = g >> 11, n = g & 2047;
            int b = bh >> 3, hh = bh & 7;
            __half hi, lo;
            split_f16(sm[row][d * 3 + c], hi, lo);
            long dst = ((long)b * Jb + n * 3 + c) * DI + hh * 64 + d;
            h[dst] = hi; l[dst] = lo;
        }
    }
}

// ---------------------------------------------------------------------------
// GEMM mainloop, 2-stage pipelined, fp16 3-product split.
// ---------------------------------------------------------------------------
__device__ __forceinline__ void gemm_issue(
    uint32_t sb, int tid, int stage, int i0,
    const __half* __restrict__ wh, const __half* __restrict__ wl,
    const __half* __restrict__ xh, const __half* __restrict__ xl,
    int ktot)
{
    const uint32_t b0 = sb + stage * G_STG;
    #pragma unroll
    for (int s = 0; s < 4; ++s) {
        int l = tid + s * 256;
        int row = l >> 3, sg = l & 7;
        uint32_t doff = (uint32_t)(row * G_LDW + sg * 8) * 2;
        long g = (long)row * ktot + i0 + sg * 8;
        cpa16(b0 + doff, wh + g);
        cpa16(b0 + 18432 + doff, wl + g);
    }
    #pragma unroll
    for (int s = 0; s < 6; ++s) {
        int l = tid + s * 256;
        int row = l >> 3, sg = l & 7;
        uint32_t doff = (uint32_t)(row * G_LDW + sg * 8) * 2;
        long g = (long)row * ktot + i0 + sg * 8;
        cpa16(b0 + 36864 + doff, xh + g);
        cpa16(b0 + 64512 + doff, xl + g);
    }
}

__device__ __forceinline__ void gemm_main(
    uint32_t sb, int tid,
    const __half* __restrict__ wh, const __half* __restrict__ wl,
    const __half* __restrict__ xh, const __half* __restrict__ xl,
    int ktot, float acc[4][6][4])
{
    const int lane = tid & 31, w = tid >> 5;
    const int wm = w >> 2, wn = w & 3;
    const int lrow = lane & 15, lc8 = (lane >> 4) << 3;
    const int nch = ktot >> 6;

    gemm_issue(sb, tid, 0, 0, wh, wl, xh, xl, ktot);
    cpa_commit();

    for (int ch = 0; ch < nch; ++ch) {
        if (ch + 1 < nch) {
            gemm_issue(sb, tid, (ch + 1) & 1, (ch + 1) * 64, wh, wl, xh, xl, ktot);
            cpa_commit();
            cpa_wait1();
        } else {
            cpa_wait0();
        }
        __syncthreads();

        const uint32_t b0 = sb + (ch & 1) * G_STG;
        #pragma unroll
        for (int ks = 0; ks < 4; ++ks) {
            const int kcol = ks * 16 + lc8;
            uint32_t ah_[4][4], al_[4][4];
            #pragma unroll
            for (int mt = 0; mt < 4; ++mt) {
                uint32_t r = (uint32_t)((wm * 64 + mt * 16 + lrow) * G_LDW + kcol) * 2;
                ldm4(ah_[mt][0], ah_[mt][1], ah_[mt][2], ah_[mt][3], b0 + r);
                ldm4(al_[mt][0], al_[mt][1], al_[mt][2], al_[mt][3], b0 + 18432 + r);
            }
            uint32_t bh_[6][2], bl_[6][2];
            #pragma unroll
            for (int g = 0; g < 3; ++g) {
                uint32_t r = (uint32_t)((wn * 48 + g * 16 + lrow) * G_LDW + kcol) * 2;
                uint32_t b0r, b1r, b2r, b3r;
                ldm4(b0r, b1r, b2r, b3r, b0 + 36864 + r);
                bh_[2*g][0] = b0r; bh_[2*g][1] = b2r;
                bh_[2*g+1][0] = b1r; bh_[2*g+1][1] = b3r;
                ldm4(b0r, b1r, b2r, b3r, b0 + 64512 + r);
                bl_[2*g][0] = b0r; bl_[2*g][1] = b2r;
                bl_[2*g+1][0] = b1r; bl_[2*g+1][1] = b3r;
            }
            #pragma unroll
            for (int mt = 0; mt < 4; ++mt)
                #pragma unroll
                for (int nt = 0; nt < 6; ++nt) {
                    mma16816(acc[mt][nt], ah_[mt], bh_[nt]);
                    mma16816(acc[mt][nt], ah_[mt], bl_[nt]);
                    mma16816(acc[mt][nt], al_[mt], bh_[nt]);
                }
        }
        __syncthreads();
    }
}

// ---------------------------------------------------------------------------
// QKV projection GEMM
// ---------------------------------------------------------------------------
__global__ __launch_bounds__(256, 1)
void qkv_mm(const __half* __restrict__ wh, const __half* __restrict__ wl,
            const __half* __restrict__ xh, const __half* __restrict__ xl,
            __half* __restrict__ qh, __half* __restrict__ ql,
            __half* __restrict__ kh, __half* __restrict__ kl,
            __half* __restrict__ vh, __half* __restrict__ vl)
{
    extern __shared__ __align__(16) char sm[];
    const uint32_t sb = s2u(sm);
    const int tid = threadIdx.x, lane = tid & 31, w = tid >> 5;
    const int wm = w >> 2, wn = w & 3;
    const int jt = blockIdx.x, ot = blockIdx.y;
    const int b = jt >> 5, o0 = ot * 128;
    const int m = o0 >> 9;

    float acc[4][6][4] = {};
    gemm_main(sb, tid,
              wh + (long)o0 * Cc, wl + (long)o0 * Cc,
              xh + ((long)b * Jb + (jt & 31) * 192) * Cc,
              xl + ((long)b * Jb + (jt & 31) * 192) * Cc,
              Cc, acc);

    __half* oh = (m == 0) ? qh : (m == 1) ? kh : vh;
    __half* ol = (m == 0) ? ql : (m == 1) ? kl : vl;

    #pragma unroll
    for (int mt = 0; mt < 4; ++mt)
        #pragma unroll
        for (int nt = 0; nt < 6; ++nt)
            #pragma unroll
            for (int e = 0; e < 4; ++e) {
                int rloc = wm * 64 + mt * 16 + (lane >> 2) + ((e >> 1) << 3);
                int cloc = wn * 48 + nt * 8 + (lane & 3) * 2 + (e & 1);
                int o_in = (o0 & 511) + rloc;
                int hh = o_in >> 6, d = o_in & 63;
                int bh = b * 8 + hh;
                int jb = (jt & 31) * 192 + cloc;
                int n = jb / 3, c = jb - 3 * n;
                __half hi, lo;
                split_f16(acc[mt][nt][e], hi, lo);
                long idx;
                if (m < 2) idx = ((long)bh * Nn + n) * Ee + d * 3 + c;
                else       idx = ((long)bh * Ee + d * 3 + c) * Nn + n;
                oh[idx] = hi; ol[idx] = lo;
            }
}

// ---------------------------------------------------------------------------
// Output projection GEMM
// ---------------------------------------------------------------------------
__global__ __launch_bounds__(256, 1)
void out_mm(const __half* __restrict__ wh, const __half* __restrict__ wl,
            const __half* __restrict__ xh, const __half* __restrict__ xl,
            float* __restrict__ y)
{
    extern __shared__ __align__(16) char sm[];
    const uint32_t sb = s2u(sm);
    const int tid = threadIdx.x, lane = tid & 31, w = tid >> 5;
    const int wm = w >> 2, wn = w & 3;
    const int jt = blockIdx.x, ot = blockIdx.y;
    const int b = jt >> 5, o0 = ot * 128;

    float acc[4][6][4] = {};
    gemm_main(sb, tid,
              wh + (long)o0 * DI, wl + (long)o0 * DI,
              xh + ((long)b * Jb + (jt & 31) * 192) * DI,
              xl + ((long)b * Jb + (jt & 31) * 192) * DI,
              DI, acc);

    #pragma unroll
    for (int mt = 0; mt < 4; ++mt)
        #pragma unroll
        for (int nt = 0; nt < 6; ++nt)
            #pragma unroll
            for (int e = 0; e < 4; ++e) {
                int rloc = wm * 64 + mt * 16 + (lane >> 2) + ((e >> 1) << 3);
                int cloc = wn * 48 + nt * 8 + (lane & 3) * 2 + (e & 1);
                int o = o0 + rloc;
                int jb = (jt & 31) * 192 + cloc;
                int n = jb / 3, c = jb - 3 * n;
                y[((long)(b * Nn + n) * Cc + o) * 3 + c] = acc[mt][nt][e];
            }
}

// ---------------------------------------------------------------------------
// Fused flash attention, 2-stage pipelined, j-chunk 32.
// QK: S = (Qh + Ql) * Kh  (2 MMAs; Kl dropped, err ~2^-12 on K side)
// AV: O += Pf16 * (Vh + Vl)  (2 MMAs; P single fp16)
// ---------------------------------------------------------------------------
__device__ __forceinline__ void flash_issue(
    uint32_t sb, int tid, int jc, int stage,
    const __half* __restrict__ Kh,
    const __half* __restrict__ Vh, const __half* __restrict__ Vl)
{
    const uint32_t kb = sb + F_KV0 + stage * F_STG;
    #pragma unroll
    for (int it = 0; it < 3; ++it) {
        int s = tid + it * 256;
        int row = s / 24, seg = s - row * 24;          // K: 32 rows x 24 segs
        uint32_t doff = (uint32_t)(row * F_LDQ + seg * 8) * 2;
        long g = (long)(jc + row) * Ee + seg * 8;
        cpa16(kb + doff, Kh + g);
    }
    #pragma unroll
    for (int it = 0; it < 3; ++it) {
        int s = tid + it * 256;
        int row = s >> 2, seg = s & 3;                 // V: 192 rows x 4 segs
        uint32_t doff = (uint32_t)(row * F_LDV + seg * 8) * 2;
        long g = (long)row * Nn + jc + seg * 8;
        cpa16(kb + 12800 + doff, Vh + g);
        cpa16(kb + 28160 + doff, Vl + g);
    }
}

__global__ __launch_bounds__(256, 1)
void vn_flash(const __half* __restrict__ qh, const __half* __restrict__ ql,
              const __half* __restrict__ kh,
              const __half* __restrict__ vh, const __half* __restrict__ vl,
              float* __restrict__ ao, float scale)
{
    extern __shared__ __align__(16) char sm[];
    const uint32_t sb = s2u(sm);
    const int tid = threadIdx.x, lane = tid & 31, w = tid >> 5;
    const int i0 = blockIdx.x * 128, bh = blockIdx.y;
    const int lrow = lane & 15, lc8 = (lane >> 4) << 3;

    const __half* Kh = kh + (long)bh * Nn * Ee;
    const __half* Vh = vh + (long)bh * Ee * Nn;
    const __half* Vl = vl + (long)bh * Ee * Nn;

    // stage Q (128 x 192 hi/lo) + first K/V chunk, one commit group
    {
        const __half* Qh = qh + ((long)bh * Nn + i0) * Ee;
        const __half* Ql = ql + ((long)bh * Nn + i0) * Ee;
        for (int s = tid; s < 128 * 24; s += 256) {
            int row = s / 24, seg = s - row * 24;
            uint32_t doff = (uint32_t)(row * F_LDQ + seg * 8) * 2;
            long g = (long)row * Ee + seg * 8;
            cpa16(sb + F_OQH + doff, Qh + g);
            cpa16(sb + F_OQL + doff, Ql + g);
        }
    }
    flash_issue(sb, tid, 0, 0, Kh, Vh, Vl);
    cpa_commit();

    float O[24][4];
    #pragma unroll
    for (int i = 0; i < 24; ++i) { O[i][0]=0.f; O[i][1]=0.f; O[i][2]=0.f; O[i][3]=0.f; }
    float m0 = -1e30f, m1 = -1e30f, l0 = 0.f, l1 = 0.f;

    for (int ch = 0; ch < 64; ++ch) {
        if (ch < 63) {
            flash_issue(sb, tid, (ch + 1) * 32, (ch + 1) & 1, Kh, Vh, Vl);
            cpa_commit();
            cpa_wait1();
        } else {
            cpa_wait0();
        }
        __syncthreads();

        const uint32_t kb = sb + F_KV0 + (ch & 1) * F_STG;

        // ---- S = q k^T  (16 rows x 32 cols per warp; 2-product) ----
        float S[4][4];
        #pragma unroll
        for (int i = 0; i < 4; ++i) { S[i][0]=0.f; S[i][1]=0.f; S[i][2]=0.f; S[i][3]=0.f; }
        #pragma unroll
        for (int ks = 0; ks < 12; ++ks) {
            const int kcol = ks * 16 + lc8;
            uint32_t qah[4], qal[4];
            uint32_t r = (uint32_t)((w * 16 + lrow) * F_LDQ + kcol) * 2;
            ldm4(qah[0], qah[1], qah[2], qah[3], sb + F_OQH + r);
            ldm4(qal[0], qal[1], qal[2], qal[3], sb + F_OQL + r);
            #pragma unroll
            for (int g = 0; g < 2; ++g) {
                uint32_t rb = (uint32_t)((g * 16 + lrow) * F_LDQ + kcol) * 2;
                uint32_t b0, b1, b2, b3;
                ldm4(b0, b1, b2, b3, kb + rb);
                uint32_t bh0[2] = {b0, b2}, bh1[2] = {b1, b3};
                mma16816(S[2*g],   qah, bh0);
                mma16816(S[2*g],   qal, bh0);
                mma16816(S[2*g+1], qah, bh1);
                mma16816(S[2*g+1], qal, bh1);
            }
        }

        // ---- online softmax ----
        float pm0 = -1e30f, pm1 = -1e30f;
        #pragma unroll
        for (int nt = 0; nt < 4; ++nt) {
            S[nt][0] *= scale; S[nt][1] *= scale; S[nt][2] *= scale; S[nt][3] *= scale;
            pm0 = fmaxf(pm0, fmaxf(S[nt][0], S[nt][1]));
            pm1 = fmaxf(pm1, fmaxf(S[nt][2], S[nt][3]));
        }
        pm0 = fmaxf(pm0, __shfl_xor_sync(0xffffffffu, pm0, 1));
        pm0 = fmaxf(pm0, __shfl_xor_sync(0xffffffffu, pm0, 2));
        pm1 = fmaxf(pm1, __shfl_xor_sync(0xffffffffu, pm1, 1));
        pm1 = fmaxf(pm1, __shfl_xor_sync(0xffffffffu, pm1, 2));
        const float nm0 = fmaxf(m0, pm0), nm1 = fmaxf(m1, pm1);
        const float a0 = __expf(m0 - nm0), a1 = __expf(m1 - nm1);
        float rs0 = 0.f, rs1 = 0.f;
        #pragma unroll
        for (int nt = 0; nt < 4; ++nt) {
            S[nt][0] = __expf(S[nt][0] - nm0);
            S[nt][1] = __expf(S[nt][1] - nm0);
            S[nt][2] = __expf(S[nt][2] - nm1);
            S[nt][3] = __expf(S[nt][3] - nm1);
            rs0 += S[nt][0] + S[nt][1];
            rs1 += S[nt][2] + S[nt][3];
        }
        rs0 += __shfl_xor_sync(0xffffffffu, rs0, 1);
        rs0 += __shfl_xor_sync(0xffffffffu, rs0, 2);
        rs1 += __shfl_xor_sync(0xffffffffu, rs1, 1);
        rs1 += __shfl_xor_sync(0xffffffffu, rs1, 2);
        l0 = l0 * a0 + rs0;
        l1 = l1 * a1 + rs1;
        m0 = nm0; m1 = nm1;
        #pragma unroll
        for (int nt = 0; nt < 24; ++nt) {
            O[nt][0] *= a0; O[nt][1] *= a0; O[nt][2] *= a1; O[nt][3] *= a1;
        }

        // ---- pack P single fp16 (C-frag -> A-frag identity) ----
        uint32_t pa[2][4];
        #pragma unroll
        for (int ks = 0; ks < 2; ++ks) {
            const int e2 = 2 * ks, o2 = 2 * ks + 1;
            pa[ks][0] = pack_f16x2(S[e2][0], S[e2][1]);
            pa[ks][1] = pack_f16x2(S[e2][2], S[e2][3]);
            pa[ks][2] = pack_f16x2(S[o2][0], S[o2][1]);
            pa[ks][3] = pack_f16x2(S[o2][2], S[o2][3]);
        }

        // ---- O += P @ (Vh + Vl) ----
        #pragma unroll
        for (int ks = 0; ks < 2; ++ks) {
            const int kcol = ks * 16 + lc8;
            #pragma unroll
            for (int gg = 0; gg < 12; ++gg) {
                uint32_t rb = (uint32_t)((gg * 16 + lrow) * F_LDV + kcol) * 2;
                uint32_t b0, b1, b2, b3;
                ldm4(b0, b1, b2, b3, kb + 12800 + rb);
                uint32_t vh0[2] = {b0, b2}, vh1[2] = {b1, b3};
                ldm4(b0, b1, b2, b3, kb + 28160 + rb);
                uint32_t vl0[2] = {b0, b2}, vl1[2] = {b1, b3};
                mma16816(O[2*gg],   pa[ks], vh0);
                mma16816(O[2*gg],   pa[ks], vl0);
                mma16816(O[2*gg+1], pa[ks], vh1);
                mma16816(O[2*gg+1], pa[ks], vl1);
            }
        }
        __syncthreads();
    }

    // ---- epilogue ----
    const float inv0 = 1.f / l0, inv1 = 1.f / l1;
    const int rowg = i0 + w * 16 + (lane >> 2);
    const long base = ((long)bh * Nn + rowg) * Ee;
    #pragma unroll
    for (int nt = 0; nt < 24; ++nt) {
        int col = nt * 8 + (lane & 3) * 2;
        *(float2*)(ao + base + col) =
            make_float2(O[nt][0] * inv0, O[nt][1] * inv0);
        *(float2*)(ao + base + 8L * Ee + col) =
            make_float2(O[nt][2] * inv1, O[nt][3] * inv1);
    }
}

// ---------------------------------------------------------------------------
extern "C" void kernel_launch(void* const* d_in, const int* in_sizes, int n_in,
                              void* d_out, int out_size)
{
    const float* x  = (const float*)d_in[0];
    const float* Wq = (const float*)d_in[1];
    const float* Wk = (const float*)d_in[2];
    const float* Wv = (const float*)d_in[3];
    const float* Wo = (const float*)d_in[4];
    float* y = (float*)d_out;

    __half *qh, *ql, *kh, *kl, *vh, *vl;
    __half *wh, *wl, *woh, *wol, *xth, *xtl, *aoth, *aotl;
    float *ao;
    cudaGetSymbolAddress((void**)&qh,   g_qh);
    cudaGetSymbolAddress((void**)&ql,   g_ql);
    cudaGetSymbolAddress((void**)&kh,   g_kh);
    cudaGetSymbolAddress((void**)&kl,   g_kl);
    cudaGetSymbolAddress((void**)&vh,   g_vh);
    cudaGetSymbolAddress((void**)&vl,   g_vl);
    cudaGetSymbolAddress((void**)&ao,   g_ao);
    cudaGetSymbolAddress((void**)&wh,   g_wh);
    cudaGetSymbolAddress((void**)&wl,   g_wl);
    cudaGetSymbolAddress((void**)&woh,  g_woh);
    cudaGetSymbolAddress((void**)&wol,  g_wol);
    cudaGetSymbolAddress((void**)&xth,  g_xth);
    cudaGetSymbolAddress((void**)&xtl,  g_xtl);
    cudaGetSymbolAddress((void**)&aoth, g_aoth);
    cudaGetSymbolAddress((void**)&aotl, g_aotl);

    cudaFuncSetAttribute(vn_flash, cudaFuncAttributeMaxDynamicSharedMemorySize, F_SMEM);
    cudaFuncSetAttribute(qkv_mm,   cudaFuncAttributeMaxDynamicSharedMemorySize, G_SMEM);
    cudaFuncSetAttribute(out_mm,   cudaFuncAttributeMaxDynamicSharedMemorySize, G_SMEM);

    dim3 blk(256);

    const int WN = DI * Cc;
    split_arr<<<(WN + 1023) / 1024, blk>>>(Wq, wh, wl, WN);
    split_arr<<<(WN + 1023) / 1024, blk>>>(Wk, wh + WN, wl + WN, WN);
    split_arr<<<(WN + 1023) / 1024, blk>>>(Wv, wh + 2 * WN, wl + 2 * WN, WN);
    split_arr<<<(WN + 1023) / 1024, blk>>>(Wo, woh, wol, WN);
    prep_x<<<Bsz * Nn, blk>>>(x, xth, xtl);

    qkv_mm<<<dim3(64, 12), blk, G_SMEM>>>(wh, wl, xth, xtl,
                                          qh, ql, kh, kl, vh, vl);

    const float scale = 1.0f / sqrtf((float)Ee);
    vn_flash<<<dim3(Nn / 128, BH), blk, F_SMEM>>>(qh, ql, kh, vh, vl, ao, scale);

    prep_ao<<<BH * Nn / 4, blk>>>(ao, aoth, aotl);
    out_mm<<<dim3(64, 2), blk, G_SMEM>>>(woh, wol, aoth, aotl, y);
}